// round 12
// baseline (speedup 1.0000x reference)
#include <cuda_runtime.h>
#include <cuda_bf16.h>
#include <math.h>
#include <stdint.h>

#define D 128
#define MAXN 100000
#define MAXE 600000
#define NBLK 782   // ceil(MAXN/128)

// ---------------- static device scratch (no allocs allowed) ----------------
__device__ float g_h0[(size_t)MAXN * D];
__device__ float g_h1[(size_t)MAXN * D];
__device__ int   g_cnt[MAXN];
__device__ int   g_off[MAXN + 1];
__device__ int   g_cur[MAXN];
__device__ int   g_src[MAXE];
__device__ int   g_bsum[1024];
// 12 pre-swizzled weight images: (3 layers x {Wl,Wr} x {hi,lo}), each 128k x 128n bf16
__device__ __nv_bfloat16 g_wimg[12 * 16384];
// A-operand images (pre-swizzled, per 128-row block: 128 rows x 2 k-halves x 128B)
__device__ __nv_bfloat16 g_mimg_h[(size_t)NBLK * 16384];
__device__ __nv_bfloat16 g_mimg_l[(size_t)NBLK * 16384];
__device__ __nv_bfloat16 g_ximg_h[(size_t)NBLK * 16384];
__device__ __nv_bfloat16 g_ximg_l[(size_t)NBLK * 16384];
__device__ __nv_bfloat16 g_yimg_h[(size_t)NBLK * 16384];
__device__ __nv_bfloat16 g_yimg_l[(size_t)NBLK * 16384];

// ---------------- helpers ----------------
__device__ __forceinline__ uint32_t smem_u32(const void* p) {
    uint32_t a;
    asm("{ .reg .u64 t; cvta.to.shared.u64 t, %1; cvt.u32.u64 %0, t; }" : "=r"(a) : "l"(p));
    return a;
}
__device__ __forceinline__ void cp16(uint32_t s, const void* g) {
    asm volatile("cp.async.cg.shared.global [%0], [%1], 16;" :: "r"(s), "l"(g));
}
__device__ __forceinline__ void ldsm_x4(uint32_t* r, uint32_t addr) {
    asm volatile("ldmatrix.sync.aligned.m8n8.x4.shared.b16 {%0,%1,%2,%3}, [%4];"
                 : "=r"(r[0]), "=r"(r[1]), "=r"(r[2]), "=r"(r[3]) : "r"(addr));
}
__device__ __forceinline__ void ldsm_x4_t(uint32_t* r, uint32_t addr) {
    asm volatile("ldmatrix.sync.aligned.m8n8.x4.trans.shared.b16 {%0,%1,%2,%3}, [%4];"
                 : "=r"(r[0]), "=r"(r[1]), "=r"(r[2]), "=r"(r[3]) : "r"(addr));
}
__device__ __forceinline__ void mma_bf16(float* c, const uint32_t* a, const uint32_t* b) {
    asm volatile(
        "mma.sync.aligned.m16n8k16.row.col.f32.bf16.bf16.f32 "
        "{%0,%1,%2,%3}, {%4,%5,%6,%7}, {%8,%9}, {%0,%1,%2,%3};"
        : "+f"(c[0]), "+f"(c[1]), "+f"(c[2]), "+f"(c[3])
        : "r"(a[0]), "r"(a[1]), "r"(a[2]), "r"(a[3]), "r"(b[0]), "r"(b[1]));
}

// A-image byte offset: block, k-half, row (0..127), k within half (0..63)
__device__ __forceinline__ uint32_t a_img_byte(int b, int kh, int r, int kp) {
    return (uint32_t)b * 32768u + (uint32_t)kh * 16384u + (uint32_t)r * 128u
         + ((uint32_t)((kp >> 3) ^ (r & 7)) << 4) + ((uint32_t)(kp & 7) << 1);
}

// store 4 consecutive cols (col0 = 4*lane) of a node as bf16 hi/lo pairs
__device__ __forceinline__ void store_a_quad(__nv_bfloat16* ih, __nv_bfloat16* il,
                                             int node, int lane, float4 v) {
    int b = node >> 7, r = node & 127;
    int col = lane << 2;
    uint32_t byte = a_img_byte(b, col >> 6, r, col & 63);
    __nv_bfloat16 h0 = __float2bfloat16(v.x), h1 = __float2bfloat16(v.y);
    __nv_bfloat16 h2 = __float2bfloat16(v.z), h3 = __float2bfloat16(v.w);
    __nv_bfloat162 hp0; hp0.x = h0; hp0.y = h1;
    __nv_bfloat162 hp1; hp1.x = h2; hp1.y = h3;
    __nv_bfloat162 lp0;
    lp0.x = __float2bfloat16(v.x - __bfloat162float(h0));
    lp0.y = __float2bfloat16(v.y - __bfloat162float(h1));
    __nv_bfloat162 lp1;
    lp1.x = __float2bfloat16(v.z - __bfloat162float(h2));
    lp1.y = __float2bfloat16(v.w - __bfloat162float(h3));
    char* ph = (char*)ih + byte;
    char* pl = (char*)il + byte;
    *(__nv_bfloat162*)(ph)     = hp0;
    *(__nv_bfloat162*)(ph + 4) = hp1;
    *(__nv_bfloat162*)(pl)     = lp0;
    *(__nv_bfloat162*)(pl + 4) = lp1;
}

// ---------------- CSR construction ----------------
__global__ void count_kernel(const int* __restrict__ dst, int* cnt, int E) {
    int e = blockIdx.x * blockDim.x + threadIdx.x;
    if (e < E) atomicAdd(&cnt[dst[e]], 1);
}

__global__ void bsum_kernel(const int* __restrict__ cnt, int* bsum, int N) {
    __shared__ int red[32];
    int i = blockIdx.x * 1024 + threadIdx.x;
    int v = (i < N) ? cnt[i] : 0;
#pragma unroll
    for (int o = 16; o > 0; o >>= 1) v += __shfl_down_sync(0xffffffff, v, o);
    if ((threadIdx.x & 31) == 0) red[threadIdx.x >> 5] = v;
    __syncthreads();
    if (threadIdx.x < 32) {
        int s = red[threadIdx.x];
#pragma unroll
        for (int o = 16; o > 0; o >>= 1) s += __shfl_down_sync(0xffffffff, s, o);
        if (threadIdx.x == 0) bsum[blockIdx.x] = s;
    }
}

__global__ void scan_bsum_kernel(int* bsum, int* off, int nb, int N) {
    __shared__ int s[1024];
    int t = threadIdx.x;
    int v = (t < nb) ? bsum[t] : 0;
    s[t] = v;
    __syncthreads();
    for (int d = 1; d < 1024; d <<= 1) {
        int x = (t >= d) ? s[t - d] : 0;
        __syncthreads();
        s[t] += x;
        __syncthreads();
    }
    if (t < nb) bsum[t] = s[t] - v;       // exclusive
    if (t == 1023) off[N] = s[1023];
}

__global__ void scan_final_kernel(const int* __restrict__ cnt, const int* __restrict__ bsum,
                                  int* off, int* cur, int N) {
    __shared__ int s[1024];
    int t = threadIdx.x;
    int i = blockIdx.x * 1024 + t;
    int v = (i < N) ? cnt[i] : 0;
    s[t] = v;
    __syncthreads();
    for (int d = 1; d < 1024; d <<= 1) {
        int x = (t >= d) ? s[t - d] : 0;
        __syncthreads();
        s[t] += x;
        __syncthreads();
    }
    if (i < N) {
        int excl = s[t] - v + bsum[blockIdx.x];
        off[i] = excl;
        cur[i] = excl;
    }
}

__global__ void fill_kernel(const int* __restrict__ src, const int* __restrict__ dst,
                            int* cur, int* out, int E) {
    int e = blockIdx.x * blockDim.x + threadIdx.x;
    if (e < E) {
        int d = dst[e];
        int pos = atomicAdd(&cur[d], 1);
        out[pos] = src[e];
    }
}

// ---------------- aggregation: warp-per-node CSR mean -> bf16 hi/lo image --
__global__ __launch_bounds__(256) void agg_kernel(
    const float* __restrict__ h,
    __nv_bfloat16* __restrict__ img_h, __nv_bfloat16* __restrict__ img_l,
    const int* __restrict__ off, const int* __restrict__ srcs, int N)
{
    int gw = (blockIdx.x * 256 + threadIdx.x) >> 5;
    int lane = threadIdx.x & 31;
    if (gw >= N) return;

    int s = __ldg(&off[gw]);
    int e = __ldg(&off[gw + 1]);

    float4 acc = make_float4(0.f, 0.f, 0.f, 0.f);
    int k = s;
    for (; k + 4 <= e; k += 4) {
        int u0 = __ldg(&srcs[k]);
        int u1 = __ldg(&srcs[k + 1]);
        int u2 = __ldg(&srcs[k + 2]);
        int u3 = __ldg(&srcs[k + 3]);
        float4 a = __ldg((const float4*)(h + (size_t)u0 * D + lane * 4));
        float4 b = __ldg((const float4*)(h + (size_t)u1 * D + lane * 4));
        float4 c = __ldg((const float4*)(h + (size_t)u2 * D + lane * 4));
        float4 d = __ldg((const float4*)(h + (size_t)u3 * D + lane * 4));
        acc.x += (a.x + b.x) + (c.x + d.x);
        acc.y += (a.y + b.y) + (c.y + d.y);
        acc.z += (a.z + b.z) + (c.z + d.z);
        acc.w += (a.w + b.w) + (c.w + d.w);
    }
    for (; k < e; ++k) {
        int u = __ldg(&srcs[k]);
        float4 a = __ldg((const float4*)(h + (size_t)u * D + lane * 4));
        acc.x += a.x; acc.y += a.y; acc.z += a.z; acc.w += a.w;
    }
    float ic = 1.0f / (float)max(e - s, 1);
    acc.x *= ic; acc.y *= ic; acc.z *= ic; acc.w *= ic;
    store_a_quad(img_h, img_l, gw, lane, acc);
}

// ---------------- x -> bf16 hi/lo image ----------------
__global__ void prep_x_kernel(const float* __restrict__ x,
                              __nv_bfloat16* __restrict__ ih,
                              __nv_bfloat16* __restrict__ il, int N)
{
    int i = blockIdx.x * 256 + threadIdx.x;
    int node = i >> 5;
    int lane = i & 31;
    if (node >= N) return;
    float4 v = __ldg((const float4*)(x + (size_t)node * D + lane * 4));
    store_a_quad(ih, il, node, lane, v);
}

// ---------------- weight prep (all 6 matrices in one launch) ---------------
__global__ void prep_w_kernel(const float* W0, const float* W1, const float* W2,
                              const float* W3, const float* W4, const float* W5,
                              __nv_bfloat16* __restrict__ wimg)
{
    int gi = blockIdx.x * 256 + threadIdx.x;
    if (gi >= 6 * 16384) return;
    int m = gi >> 14;
    int i = gi & 16383;
    const float* Ws[6] = {W0, W1, W2, W3, W4, W5};
    int k = i >> 7;
    int n = i & 127;
    float x = __ldg(Ws[m] + k * 128 + n);
    __nv_bfloat16 h = __float2bfloat16(x);
    float l = x - __bfloat162float(h);
    uint32_t byte = (uint32_t)(k >> 6) * 16384u + (uint32_t)(k & 63) * 256u
                  + ((uint32_t)((n >> 3) ^ (k & 7)) << 4) + (uint32_t)(n & 7) * 2u;
    __nv_bfloat16* hi = wimg + (size_t)(2 * m) * 16384;
    __nv_bfloat16* lo = hi + 16384;
    hi[byte >> 1] = h;
    lo[byte >> 1] = __float2bfloat16(l);
}

// ---------------- HMMA GEMM: relu([mean|h] @ [Wl;Wr] + b), bf16 split-3 ----
// 512 threads, 1 CTA/SM, 2-stage double-buffered cp.async pipeline.
// CTA: 128 rows x 128 cols, K=256 in 4 chunks of 64. 16 warps, warp = 32x32.
#define GT 512
#define STG_BYTES 65536   // per-stage: AHI 16K | ALO 16K | WHI 16K | WLO 16K
#define SM_TOT (2 * STG_BYTES)

__global__ __launch_bounds__(GT, 1) void gemm_mma_kernel(
    const __nv_bfloat16* __restrict__ mh, const __nv_bfloat16* __restrict__ ml,
    const __nv_bfloat16* __restrict__ hh, const __nv_bfloat16* __restrict__ hl,
    float* __restrict__ h_out,
    const __nv_bfloat16* __restrict__ wlhi, const __nv_bfloat16* __restrict__ wllo,
    const __nv_bfloat16* __restrict__ wrhi, const __nv_bfloat16* __restrict__ wrlo,
    const float* __restrict__ bias,
    __nv_bfloat16* __restrict__ oih, __nv_bfloat16* __restrict__ oil,
    int write_img, int N)
{
    extern __shared__ char smem[];
    const uint32_t sb = smem_u32(smem);
    const int t = threadIdx.x;
    const int lane = t & 31;
    const int w = t >> 5;               // 0..15
    const int wrow = (w & 3) * 32;
    const int wcol = (w >> 2) * 32;
    const int row0 = blockIdx.x * 128;

    const __nv_bfloat16* aih[2] = {mh, hh};
    const __nv_bfloat16* ail[2] = {ml, hl};
    const __nv_bfloat16* whis[2] = {wlhi, wrhi};
    const __nv_bfloat16* wlos[2] = {wllo, wrlo};

    float C[32];                         // [mf 2][nf 4][4]
#pragma unroll
    for (int i = 0; i < 32; ++i) C[i] = 0.f;

    const int rsel = (lane & 7) + ((lane >> 3) & 1) * 8;
    const int usel = lane >> 4;

    // ---- stage chunk c into buffer (c&1): 4096 x 16B cp.async ----
    auto stage_chunk = [&](int c) {
        const int mat = c >> 1, kh = c & 1;
        const char* s4[4];
        s4[0] = (const char*)aih[mat] + (size_t)blockIdx.x * 32768 + kh * 16384;
        s4[1] = (const char*)ail[mat] + (size_t)blockIdx.x * 32768 + kh * 16384;
        s4[2] = (const char*)whis[mat] + kh * 16384;
        s4[3] = (const char*)wlos[mat] + kh * 16384;
        uint32_t sbuf = sb + (uint32_t)(c & 1) * STG_BYTES;
        for (int i = t; i < 4096; i += GT) {
            int which = i >> 10;
            uint32_t o = (uint32_t)(i & 1023) << 4;
            cp16(sbuf + (uint32_t)which * 16384u + o, s4[which] + o);
        }
        asm volatile("cp.async.commit_group;" ::: "memory");
    };

    stage_chunk(0);

    for (int chunk = 0; chunk < 4; ++chunk) {
        if (chunk + 1 < 4) {
            stage_chunk(chunk + 1);
            asm volatile("cp.async.wait_group 1;" ::: "memory");
        } else {
            asm volatile("cp.async.wait_group 0;" ::: "memory");
        }
        __syncthreads();

        const uint32_t sa = sb + (uint32_t)(chunk & 1) * STG_BYTES;        // A hi
        const uint32_t swb = sa + 32768u;                                  // W hi

        // ---- compute: 4 k-steps of 16; term-major sweeps ----
#pragma unroll
        for (int ks = 0; ks < 4; ++ks) {
            const int k0 = ks * 16;
            uint32_t ahf[2][4], alf[2][4];
#pragma unroll
            for (int mf = 0; mf < 2; ++mf) {
                int row = wrow + mf * 16 + rsel;
                uint32_t unit = (uint32_t)(((k0 >> 3) + usel) ^ (lane & 7));
                uint32_t aaddr = sa + (uint32_t)row * 128u + (unit << 4);
                ldsm_x4(ahf[mf], aaddr);
                ldsm_x4(alf[mf], aaddr + 16384u);
            }
            uint32_t bh[2][4], bl[2][4];
            const int krow = k0 + rsel;
#pragma unroll
            for (int nq = 0; nq < 2; ++nq) {
                const int n0 = wcol + nq * 16;
                uint32_t unit = (uint32_t)(((n0 >> 3) + usel) ^ (lane & 7));
                uint32_t baddr = swb + (uint32_t)krow * 256u + (unit << 4);
                ldsm_x4_t(bh[nq], baddr);
                ldsm_x4_t(bl[nq], baddr + 16384u);
            }
            // sweep 1: Ah * Wh (8 independent accumulators)
#pragma unroll
            for (int nq = 0; nq < 2; ++nq)
#pragma unroll
                for (int mf = 0; mf < 2; ++mf) {
                    mma_bf16(&C[((mf * 4 + nq * 2) << 2)],     ahf[mf], bh[nq]);
                    mma_bf16(&C[((mf * 4 + nq * 2 + 1) << 2)], ahf[mf], bh[nq] + 2);
                }
            // sweep 2: Ah * Wl
#pragma unroll
            for (int nq = 0; nq < 2; ++nq)
#pragma unroll
                for (int mf = 0; mf < 2; ++mf) {
                    mma_bf16(&C[((mf * 4 + nq * 2) << 2)],     ahf[mf], bl[nq]);
                    mma_bf16(&C[((mf * 4 + nq * 2 + 1) << 2)], ahf[mf], bl[nq] + 2);
                }
            // sweep 3: Al * Wh
#pragma unroll
            for (int nq = 0; nq < 2; ++nq)
#pragma unroll
                for (int mf = 0; mf < 2; ++mf) {
                    mma_bf16(&C[((mf * 4 + nq * 2) << 2)],     alf[mf], bh[nq]);
                    mma_bf16(&C[((mf * 4 + nq * 2 + 1) << 2)], alf[mf], bh[nq] + 2);
                }
        }
        __syncthreads();   // protect this buffer before it is restaged
    }

    // ---- epilogue: bias + relu + fp32 store + (optional) bf16 image store ----
#pragma unroll
    for (int mf = 0; mf < 2; ++mf) {
        int rloc = wrow + mf * 16 + (lane >> 2);
        int rlo = row0 + rloc;
#pragma unroll
        for (int nf = 0; nf < 4; ++nf) {
            int col = wcol + nf * 8 + (lane & 3) * 2;
            float b0 = __ldg(bias + col);
            float b1 = __ldg(bias + col + 1);
            const float* c = &C[((mf * 4 + nf) << 2)];
            float v0 = fmaxf(c[0] + b0, 0.f);
            float v1 = fmaxf(c[1] + b1, 0.f);
            float v2 = fmaxf(c[2] + b0, 0.f);
            float v3 = fmaxf(c[3] + b1, 0.f);
            if (rlo < N) {
                *(float2*)(h_out + (size_t)rlo * D + col) = make_float2(v0, v1);
                if (write_img) {
                    uint32_t byte = a_img_byte(blockIdx.x, col >> 6, rloc, col & 63);
                    __nv_bfloat16 h0 = __float2bfloat16(v0), h1 = __float2bfloat16(v1);
                    __nv_bfloat162 hp; hp.x = h0; hp.y = h1;
                    __nv_bfloat162 lp;
                    lp.x = __float2bfloat16(v0 - __bfloat162float(h0));
                    lp.y = __float2bfloat16(v1 - __bfloat162float(h1));
                    *(__nv_bfloat162*)((char*)oih + byte) = hp;
                    *(__nv_bfloat162*)((char*)oil + byte) = lp;
                }
            }
            int rhi = rlo + 8;
            if (rhi < N) {
                *(float2*)(h_out + (size_t)rhi * D + col) = make_float2(v2, v3);
                if (write_img) {
                    uint32_t byte = a_img_byte(blockIdx.x, col >> 6, rloc + 8, col & 63);
                    __nv_bfloat16 h2 = __float2bfloat16(v2), h3 = __float2bfloat16(v3);
                    __nv_bfloat162 hp; hp.x = h2; hp.y = h3;
                    __nv_bfloat162 lp;
                    lp.x = __float2bfloat16(v2 - __bfloat162float(h2));
                    lp.y = __float2bfloat16(v3 - __bfloat162float(h3));
                    *(__nv_bfloat162*)((char*)oih + byte) = hp;
                    *(__nv_bfloat162*)((char*)oil + byte) = lp;
                }
            }
        }
    }
}

// ---------------- pooled sum (sorted batch) + sigmoid head -----------------
__global__ void pool_head_kernel(const float* __restrict__ h, const int* __restrict__ batch,
                                 const float* __restrict__ Wro, const float* __restrict__ bro,
                                 float* __restrict__ out, int N)
{
    __shared__ int bounds[2];
    __shared__ float red[4];
    int g = blockIdx.x;
    int t = threadIdx.x;

    if (t < 2) {
        int target = g + t;
        int lo = 0, hi = N;
        while (lo < hi) {
            int mid = (lo + hi) >> 1;
            if (batch[mid] < target) lo = mid + 1; else hi = mid;
        }
        bounds[t] = lo;
    }
    __syncthreads();
    int s = bounds[0], e = bounds[1];

    float sum = 0.0f;
    for (int v = s; v < e; ++v) sum += h[(size_t)v * D + t];
    float val = sum * __ldg(&Wro[t]);
#pragma unroll
    for (int o = 16; o > 0; o >>= 1) val += __shfl_xor_sync(0xffffffff, val, o);
    if ((t & 31) == 0) red[t >> 5] = val;
    __syncthreads();
    if (t == 0) {
        float z = red[0] + red[1] + red[2] + red[3] + __ldg(bro);
        out[g] = 1.0f / (1.0f + expf(-z));
    }
}

// ---------------- launcher ----------------
extern "C" void kernel_launch(void* const* d_in, const int* in_sizes, int n_in,
                              void* d_out, int out_size)
{
    const float* x     = (const float*)d_in[0];
    const int*   ei    = (const int*)d_in[1];
    const int*   batch = (const int*)d_in[2];
    const float* Wl1 = (const float*)d_in[3];
    const float* Wr1 = (const float*)d_in[4];
    const float* b1  = (const float*)d_in[5];
    const float* Wl2 = (const float*)d_in[6];
    const float* Wr2 = (const float*)d_in[7];
    const float* b2  = (const float*)d_in[8];
    const float* Wl3 = (const float*)d_in[9];
    const float* Wr3 = (const float*)d_in[10];
    const float* b3  = (const float*)d_in[11];
    const float* Wro = (const float*)d_in[12];
    const float* bro = (const float*)d_in[13];
    float* out = (float*)d_out;

    int N = in_sizes[0] / D;
    int E = in_sizes[1] / 2;
    int G = out_size;

    float *h0, *h1;
    int *cnt, *off, *cur, *srcs, *bsum;
    __nv_bfloat16 *wimg, *mih, *mil, *xih, *xil, *yih, *yil;
    cudaGetSymbolAddress((void**)&h0,   g_h0);
    cudaGetSymbolAddress((void**)&h1,   g_h1);
    cudaGetSymbolAddress((void**)&cnt,  g_cnt);
    cudaGetSymbolAddress((void**)&off,  g_off);
    cudaGetSymbolAddress((void**)&cur,  g_cur);
    cudaGetSymbolAddress((void**)&srcs, g_src);
    cudaGetSymbolAddress((void**)&bsum, g_bsum);
    cudaGetSymbolAddress((void**)&wimg, g_wimg);
    cudaGetSymbolAddress((void**)&mih,  g_mimg_h);
    cudaGetSymbolAddress((void**)&mil,  g_mimg_l);
    cudaGetSymbolAddress((void**)&xih,  g_ximg_h);
    cudaGetSymbolAddress((void**)&xil,  g_ximg_l);
    cudaGetSymbolAddress((void**)&yih,  g_yimg_h);
    cudaGetSymbolAddress((void**)&yil,  g_yimg_l);

    const int* src_arr = ei;
    const int* dst_arr = ei + E;

    // prep: weights (one launch) + x image
    prep_w_kernel<<<(6 * 16384 + 255) / 256, 256>>>(Wl1, Wr1, Wl2, Wr2, Wl3, Wr3, wimg);
    prep_x_kernel<<<(N * 32 + 255) / 256, 256>>>(x, xih, xil, N);

    // CSR build (parallel 3-phase scan)
    int nb = (N + 1023) / 1024;
    cudaMemsetAsync(cnt, 0, (size_t)N * sizeof(int));
    count_kernel<<<(E + 255) / 256, 256>>>(dst_arr, cnt, E);
    bsum_kernel<<<nb, 1024>>>(cnt, bsum, N);
    scan_bsum_kernel<<<1, 1024>>>(bsum, off, nb, N);
    scan_final_kernel<<<nb, 1024>>>(cnt, bsum, off, cur, N);
    fill_kernel<<<(E + 255) / 256, 256>>>(src_arr, dst_arr, cur, srcs, E);

    cudaFuncSetAttribute((const void*)gemm_mma_kernel,
                         cudaFuncAttributeMaxDynamicSharedMemorySize, SM_TOT);
    int gblocks = (N + 127) / 128;
    int ablocks = (N * 32 + 255) / 256;

    __nv_bfloat16* im = wimg;
    // layer 1: A-h from x image, write y image
    agg_kernel<<<ablocks, 256>>>(x, mih, mil, off, srcs, N);
    gemm_mma_kernel<<<gblocks, GT, SM_TOT>>>(mih, mil, xih, xil, h0,
        im + 0 * 16384, im + 1 * 16384, im + 2 * 16384, im + 3 * 16384, b1,
        yih, yil, 1, N);
    // layer 2: A-h from y image, write x image
    agg_kernel<<<ablocks, 256>>>(h0, mih, mil, off, srcs, N);
    gemm_mma_kernel<<<gblocks, GT, SM_TOT>>>(mih, mil, yih, yil, h1,
        im + 4 * 16384, im + 5 * 16384, im + 6 * 16384, im + 7 * 16384, b2,
        xih, xil, 1, N);
    // layer 3: A-h from x image, no image write
    agg_kernel<<<ablocks, 256>>>(h1, mih, mil, off, srcs, N);
    gemm_mma_kernel<<<gblocks, GT, SM_TOT>>>(mih, mil, xih, xil, h0,
        im + 8 * 16384, im + 9 * 16384, im + 10 * 16384, im + 11 * 16384, b3,
        yih, yil, 0, N);

    // pooling + head
    pool_head_kernel<<<G, D>>>(h0, batch, Wro, bro, out, N);
}

// round 13
// speedup vs baseline: 1.1414x; 1.1414x over previous
#include <cuda_runtime.h>
#include <cuda_fp16.h>
#include <math.h>
#include <stdint.h>

#define D 128
#define MAXN 100000
#define MAXE 600000
#define NBLK 782   // ceil(MAXN/128)

// ---------------- static device scratch (no allocs allowed) ----------------
__device__ float g_h0[(size_t)MAXN * D];
__device__ float g_h1[(size_t)MAXN * D];
__device__ int   g_cnt[MAXN];
__device__ int   g_off[MAXN + 1];
__device__ int   g_cur[MAXN];
__device__ int   g_src[MAXE];
__device__ int   g_bsum[1024];
// 6 pre-swizzled fp16 weight images (3 layers x {Wl,Wr}), each 128k x 128n
__device__ __half g_wimg[6 * 16384];
// A-operand images (pre-swizzled fp16 hi/lo, per 128-row block: 2 k-halves x 16KB)
__device__ __half g_mimg_h[(size_t)NBLK * 16384];
__device__ __half g_mimg_l[(size_t)NBLK * 16384];
__device__ __half g_ximg_h[(size_t)NBLK * 16384];
__device__ __half g_ximg_l[(size_t)NBLK * 16384];
__device__ __half g_yimg_h[(size_t)NBLK * 16384];
__device__ __half g_yimg_l[(size_t)NBLK * 16384];

// ---------------- helpers ----------------
__device__ __forceinline__ uint32_t smem_u32(const void* p) {
    uint32_t a;
    asm("{ .reg .u64 t; cvta.to.shared.u64 t, %1; cvt.u32.u64 %0, t; }" : "=r"(a) : "l"(p));
    return a;
}
__device__ __forceinline__ void cp16(uint32_t s, const void* g) {
    asm volatile("cp.async.cg.shared.global [%0], [%1], 16;" :: "r"(s), "l"(g));
}
__device__ __forceinline__ void ldsm_x4(uint32_t* r, uint32_t addr) {
    asm volatile("ldmatrix.sync.aligned.m8n8.x4.shared.b16 {%0,%1,%2,%3}, [%4];"
                 : "=r"(r[0]), "=r"(r[1]), "=r"(r[2]), "=r"(r[3]) : "r"(addr));
}
__device__ __forceinline__ void ldsm_x4_t(uint32_t* r, uint32_t addr) {
    asm volatile("ldmatrix.sync.aligned.m8n8.x4.trans.shared.b16 {%0,%1,%2,%3}, [%4];"
                 : "=r"(r[0]), "=r"(r[1]), "=r"(r[2]), "=r"(r[3]) : "r"(addr));
}
__device__ __forceinline__ void mma_f16(float* c, const uint32_t* a, const uint32_t* b) {
    asm volatile(
        "mma.sync.aligned.m16n8k16.row.col.f32.f16.f16.f32 "
        "{%0,%1,%2,%3}, {%4,%5,%6,%7}, {%8,%9}, {%0,%1,%2,%3};"
        : "+f"(c[0]), "+f"(c[1]), "+f"(c[2]), "+f"(c[3])
        : "r"(a[0]), "r"(a[1]), "r"(a[2]), "r"(a[3]), "r"(b[0]), "r"(b[1]));
}

// A-image byte offset: block, k-half, row (0..127), k within half (0..63)
__device__ __forceinline__ uint32_t a_img_byte(int b, int kh, int r, int kp) {
    return (uint32_t)b * 32768u + (uint32_t)kh * 16384u + (uint32_t)r * 128u
         + ((uint32_t)((kp >> 3) ^ (r & 7)) << 4) + ((uint32_t)(kp & 7) << 1);
}

// store 4 consecutive cols (col0 = 4*lane) of a node as fp16 hi/lo pairs
__device__ __forceinline__ void store_a_quad(__half* ih, __half* il,
                                             int node, int lane, float4 v) {
    int b = node >> 7, r = node & 127;
    int col = lane << 2;
    uint32_t byte = a_img_byte(b, col >> 6, r, col & 63);
    __half h0 = __float2half(v.x), h1 = __float2half(v.y);
    __half h2 = __float2half(v.z), h3 = __float2half(v.w);
    __half2 hp0 = __halves2half2(h0, h1);
    __half2 hp1 = __halves2half2(h2, h3);
    __half2 lp0 = __halves2half2(__float2half(v.x - __half2float(h0)),
                                 __float2half(v.y - __half2float(h1)));
    __half2 lp1 = __halves2half2(__float2half(v.z - __half2float(h2)),
                                 __float2half(v.w - __half2float(h3)));
    char* ph = (char*)ih + byte;
    char* pl = (char*)il + byte;
    *(__half2*)(ph)     = hp0;
    *(__half2*)(ph + 4) = hp1;
    *(__half2*)(pl)     = lp0;
    *(__half2*)(pl + 4) = lp1;
}

// ---------------- CSR construction ----------------
__global__ void count_kernel(const int* __restrict__ dst, int* cnt, int E) {
    int e = blockIdx.x * blockDim.x + threadIdx.x;
    if (e < E) atomicAdd(&cnt[dst[e]], 1);
}

__global__ void bsum_kernel(const int* __restrict__ cnt, int* bsum, int N) {
    __shared__ int red[32];
    int i = blockIdx.x * 1024 + threadIdx.x;
    int v = (i < N) ? cnt[i] : 0;
#pragma unroll
    for (int o = 16; o > 0; o >>= 1) v += __shfl_down_sync(0xffffffff, v, o);
    if ((threadIdx.x & 31) == 0) red[threadIdx.x >> 5] = v;
    __syncthreads();
    if (threadIdx.x < 32) {
        int s = red[threadIdx.x];
#pragma unroll
        for (int o = 16; o > 0; o >>= 1) s += __shfl_down_sync(0xffffffff, s, o);
        if (threadIdx.x == 0) bsum[blockIdx.x] = s;
    }
}

__global__ void scan_bsum_kernel(int* bsum, int* off, int nb, int N) {
    __shared__ int s[1024];
    int t = threadIdx.x;
    int v = (t < nb) ? bsum[t] : 0;
    s[t] = v;
    __syncthreads();
    for (int d = 1; d < 1024; d <<= 1) {
        int x = (t >= d) ? s[t - d] : 0;
        __syncthreads();
        s[t] += x;
        __syncthreads();
    }
    if (t < nb) bsum[t] = s[t] - v;
    if (t == 1023) off[N] = s[1023];
}

__global__ void scan_final_kernel(const int* __restrict__ cnt, const int* __restrict__ bsum,
                                  int* off, int* cur, int N) {
    __shared__ int s[1024];
    int t = threadIdx.x;
    int i = blockIdx.x * 1024 + t;
    int v = (i < N) ? cnt[i] : 0;
    s[t] = v;
    __syncthreads();
    for (int d = 1; d < 1024; d <<= 1) {
        int x = (t >= d) ? s[t - d] : 0;
        __syncthreads();
        s[t] += x;
        __syncthreads();
    }
    if (i < N) {
        int excl = s[t] - v + bsum[blockIdx.x];
        off[i] = excl;
        cur[i] = excl;
    }
}

__global__ void fill_kernel(const int* __restrict__ src, const int* __restrict__ dst,
                            int* cur, int* out, int E) {
    int e = blockIdx.x * blockDim.x + threadIdx.x;
    if (e < E) {
        int d = dst[e];
        int pos = atomicAdd(&cur[d], 1);
        out[pos] = src[e];
    }
}

// ---------------- aggregation: warp-per-node CSR mean -> fp16 hi/lo image --
__global__ __launch_bounds__(256) void agg_kernel(
    const float* __restrict__ h,
    __half* __restrict__ img_h, __half* __restrict__ img_l,
    const int* __restrict__ off, const int* __restrict__ srcs, int N)
{
    int gw = (blockIdx.x * 256 + threadIdx.x) >> 5;
    int lane = threadIdx.x & 31;
    if (gw >= N) return;

    int s = __ldg(&off[gw]);
    int e = __ldg(&off[gw + 1]);

    float4 acc = make_float4(0.f, 0.f, 0.f, 0.f);
    int k = s;
    for (; k + 4 <= e; k += 4) {
        int u0 = __ldg(&srcs[k]);
        int u1 = __ldg(&srcs[k + 1]);
        int u2 = __ldg(&srcs[k + 2]);
        int u3 = __ldg(&srcs[k + 3]);
        float4 a = __ldg((const float4*)(h + (size_t)u0 * D + lane * 4));
        float4 b = __ldg((const float4*)(h + (size_t)u1 * D + lane * 4));
        float4 c = __ldg((const float4*)(h + (size_t)u2 * D + lane * 4));
        float4 d = __ldg((const float4*)(h + (size_t)u3 * D + lane * 4));
        acc.x += (a.x + b.x) + (c.x + d.x);
        acc.y += (a.y + b.y) + (c.y + d.y);
        acc.z += (a.z + b.z) + (c.z + d.z);
        acc.w += (a.w + b.w) + (c.w + d.w);
    }
    for (; k < e; ++k) {
        int u = __ldg(&srcs[k]);
        float4 a = __ldg((const float4*)(h + (size_t)u * D + lane * 4));
        acc.x += a.x; acc.y += a.y; acc.z += a.z; acc.w += a.w;
    }
    float ic = 1.0f / (float)max(e - s, 1);
    acc.x *= ic; acc.y *= ic; acc.z *= ic; acc.w *= ic;
    store_a_quad(img_h, img_l, gw, lane, acc);
}

// ---------------- x -> fp16 hi/lo image ----------------
__global__ void prep_x_kernel(const float* __restrict__ x,
                              __half* __restrict__ ih,
                              __half* __restrict__ il, int N)
{
    int i = blockIdx.x * 256 + threadIdx.x;
    int node = i >> 5;
    int lane = i & 31;
    if (node >= N) return;
    float4 v = __ldg((const float4*)(x + (size_t)node * D + lane * 4));
    store_a_quad(ih, il, node, lane, v);
}

// ---------------- weight prep (6 matrices, single fp16, one launch) --------
// Image layout (per k-chunk of 64): byte = (k>>6)*16384 + (k&63)*256
//                                        + (((n>>3) ^ (k&7)) << 4) + (n&7)*2
__global__ void prep_w_kernel(const float* W0, const float* W1, const float* W2,
                              const float* W3, const float* W4, const float* W5,
                              __half* __restrict__ wimg)
{
    int gi = blockIdx.x * 256 + threadIdx.x;
    if (gi >= 6 * 16384) return;
    int m = gi >> 14;
    int i = gi & 16383;
    const float* Ws[6] = {W0, W1, W2, W3, W4, W5};
    int k = i >> 7;
    int n = i & 127;
    float x = __ldg(Ws[m] + k * 128 + n);
    uint32_t byte = (uint32_t)(k >> 6) * 16384u + (uint32_t)(k & 63) * 256u
                  + ((uint32_t)((n >> 3) ^ (k & 7)) << 4) + (uint32_t)(n & 7) * 2u;
    __half* img = wimg + (size_t)m * 16384;
    img[byte >> 1] = __float2half(x);
}

// ---------------- HMMA GEMM: relu([mean|h] @ [Wl;Wr] + b), fp16 2-term -----
// CTA: 128 rows x 128 cols, K=256 in 4 chunks of 64. 8 warps, warp = 32x64.
// Per k-step per warp: 16 HMMA (AhW + AlW) instead of 24.
#define GT 256
#define SM_AHI 0
#define SM_ALO 16384
#define SM_W   32768
#define SM_TOT 49152

__global__ __launch_bounds__(GT, 2) void gemm_mma_kernel(
    const __half* __restrict__ mh, const __half* __restrict__ ml,
    const __half* __restrict__ hh, const __half* __restrict__ hl,
    float* __restrict__ h_out,
    const __half* __restrict__ wl, const __half* __restrict__ wr,
    const float* __restrict__ bias,
    __half* __restrict__ oih, __half* __restrict__ oil,
    int write_img, int N)
{
    extern __shared__ char smem[];
    const uint32_t sb = smem_u32(smem);
    const int t = threadIdx.x;
    const int lane = t & 31;
    const int w = t >> 5;
    const int wrow = (w & 3) * 32;
    const int wcol = (w >> 2) * 64;
    const int row0 = blockIdx.x * 128;

    const __half* aih[2] = {mh, hh};
    const __half* ail[2] = {ml, hl};
    const __half* ws[2]  = {wl, wr};

    float C[64];
#pragma unroll
    for (int i = 0; i < 64; ++i) C[i] = 0.f;

    const int rsel = (lane & 7) + ((lane >> 3) & 1) * 8;
    const int usel = lane >> 4;

    for (int chunk = 0; chunk < 4; ++chunk) {
        const int mat = chunk >> 1;   // 0: mean@Wl, 1: h@Wr
        const int kh  = chunk & 1;

        // ---- stage A hi/lo + W: 3 x 16KB pure cp.async copies ----
        const char* s3[3];
        s3[0] = (const char*)aih[mat] + (size_t)blockIdx.x * 32768 + kh * 16384;
        s3[1] = (const char*)ail[mat] + (size_t)blockIdx.x * 32768 + kh * 16384;
        s3[2] = (const char*)ws[mat] + kh * 16384;
        for (int i = t; i < 3072; i += GT) {
            int which = i >> 10;
            uint32_t o = (uint32_t)(i & 1023) << 4;
            cp16(sb + (uint32_t)which * 16384u + o, s3[which] + o);
        }
        asm volatile("cp.async.commit_group;" ::: "memory");
        asm volatile("cp.async.wait_group 0;" ::: "memory");
        __syncthreads();

        // ---- compute: 4 k-steps of 16; 2 term-major sweeps ----
#pragma unroll
        for (int ks = 0; ks < 4; ++ks) {
            const int k0 = ks * 16;
            uint32_t ahf[2][4], alf[2][4];
#pragma unroll
            for (int mf = 0; mf < 2; ++mf) {
                int row = wrow + mf * 16 + rsel;
                uint32_t unit = (uint32_t)(((k0 >> 3) + usel) ^ (lane & 7));
                uint32_t aaddr = sb + SM_AHI + (uint32_t)row * 128u + (unit << 4);
                ldsm_x4(ahf[mf], aaddr);
                ldsm_x4(alf[mf], aaddr + 16384u);
            }
            uint32_t bf[4][4];
            const int krow = k0 + rsel;
#pragma unroll
            for (int nq = 0; nq < 4; ++nq) {
                const int n0 = wcol + nq * 16;
                uint32_t unit = (uint32_t)(((n0 >> 3) + usel) ^ (lane & 7));
                uint32_t baddr = sb + SM_W + (uint32_t)krow * 256u + (unit << 4);
                ldsm_x4_t(bf[nq], baddr);
            }
            // sweep 1: Ah * W (16 independent accumulators)
#pragma unroll
            for (int nq = 0; nq < 4; ++nq)
#pragma unroll
                for (int mf = 0; mf < 2; ++mf) {
                    mma_f16(&C[((mf * 8 + nq * 2) << 2)],     ahf[mf], bf[nq]);
                    mma_f16(&C[((mf * 8 + nq * 2 + 1) << 2)], ahf[mf], bf[nq] + 2);
                }
            // sweep 2: Al * W
#pragma unroll
            for (int nq = 0; nq < 4; ++nq)
#pragma unroll
                for (int mf = 0; mf < 2; ++mf) {
                    mma_f16(&C[((mf * 8 + nq * 2) << 2)],     alf[mf], bf[nq]);
                    mma_f16(&C[((mf * 8 + nq * 2 + 1) << 2)], alf[mf], bf[nq] + 2);
                }
        }
        __syncthreads();
    }

    // ---- epilogue: bias + relu + fp32 store + (optional) fp16 image store ----
#pragma unroll
    for (int mf = 0; mf < 2; ++mf) {
        int rloc = wrow + mf * 16 + (lane >> 2);
        int rlo = row0 + rloc;
#pragma unroll
        for (int nf = 0; nf < 8; ++nf) {
            int col = wcol + nf * 8 + (lane & 3) * 2;
            float b0 = __ldg(bias + col);
            float b1 = __ldg(bias + col + 1);
            const float* c = &C[((mf * 8 + nf) << 2)];
            float v0 = fmaxf(c[0] + b0, 0.f);
            float v1 = fmaxf(c[1] + b1, 0.f);
            float v2 = fmaxf(c[2] + b0, 0.f);
            float v3 = fmaxf(c[3] + b1, 0.f);
            if (rlo < N) {
                *(float2*)(h_out + (size_t)rlo * D + col) = make_float2(v0, v1);
                if (write_img) {
                    uint32_t byte = a_img_byte(blockIdx.x, col >> 6, rloc, col & 63);
                    __half h0 = __float2half(v0), h1 = __float2half(v1);
                    *(__half2*)((char*)oih + byte) = __halves2half2(h0, h1);
                    *(__half2*)((char*)oil + byte) =
                        __halves2half2(__float2half(v0 - __half2float(h0)),
                                       __float2half(v1 - __half2float(h1)));
                }
            }
            int rhi = rlo + 8;
            if (rhi < N) {
                *(float2*)(h_out + (size_t)rhi * D + col) = make_float2(v2, v3);
                if (write_img) {
                    uint32_t byte = a_img_byte(blockIdx.x, col >> 6, rloc + 8, col & 63);
                    __half h2 = __float2half(v2), h3 = __float2half(v3);
                    *(__half2*)((char*)oih + byte) = __halves2half2(h2, h3);
                    *(__half2*)((char*)oil + byte) =
                        __halves2half2(__float2half(v2 - __half2float(h2)),
                                       __float2half(v3 - __half2float(h3)));
                }
            }
        }
    }
}

// ---------------- pooled sum (sorted batch) + sigmoid head -----------------
__global__ void pool_head_kernel(const float* __restrict__ h, const int* __restrict__ batch,
                                 const float* __restrict__ Wro, const float* __restrict__ bro,
                                 float* __restrict__ out, int N)
{
    __shared__ int bounds[2];
    __shared__ float red[4];
    int g = blockIdx.x;
    int t = threadIdx.x;

    if (t < 2) {
        int target = g + t;
        int lo = 0, hi = N;
        while (lo < hi) {
            int mid = (lo + hi) >> 1;
            if (batch[mid] < target) lo = mid + 1; else hi = mid;
        }
        bounds[t] = lo;
    }
    __syncthreads();
    int s = bounds[0], e = bounds[1];

    float sum = 0.0f;
    for (int v = s; v < e; ++v) sum += h[(size_t)v * D + t];
    float val = sum * __ldg(&Wro[t]);
#pragma unroll
    for (int o = 16; o > 0; o >>= 1) val += __shfl_xor_sync(0xffffffff, val, o);
    if ((t & 31) == 0) red[t >> 5] = val;
    __syncthreads();
    if (t == 0) {
        float z = red[0] + red[1] + red[2] + red[3] + __ldg(bro);
        out[g] = 1.0f / (1.0f + expf(-z));
    }
}

// ---------------- launcher ----------------
extern "C" void kernel_launch(void* const* d_in, const int* in_sizes, int n_in,
                              void* d_out, int out_size)
{
    const float* x     = (const float*)d_in[0];
    const int*   ei    = (const int*)d_in[1];
    const int*   batch = (const int*)d_in[2];
    const float* Wl1 = (const float*)d_in[3];
    const float* Wr1 = (const float*)d_in[4];
    const float* b1  = (const float*)d_in[5];
    const float* Wl2 = (const float*)d_in[6];
    const float* Wr2 = (const float*)d_in[7];
    const float* b2  = (const float*)d_in[8];
    const float* Wl3 = (const float*)d_in[9];
    const float* Wr3 = (const float*)d_in[10];
    const float* b3  = (const float*)d_in[11];
    const float* Wro = (const float*)d_in[12];
    const float* bro = (const float*)d_in[13];
    float* out = (float*)d_out;

    int N = in_sizes[0] / D;
    int E = in_sizes[1] / 2;
    int G = out_size;

    float *h0, *h1;
    int *cnt, *off, *cur, *srcs, *bsum;
    __half *wimg, *mih, *mil, *xih, *xil, *yih, *yil;
    cudaGetSymbolAddress((void**)&h0,   g_h0);
    cudaGetSymbolAddress((void**)&h1,   g_h1);
    cudaGetSymbolAddress((void**)&cnt,  g_cnt);
    cudaGetSymbolAddress((void**)&off,  g_off);
    cudaGetSymbolAddress((void**)&cur,  g_cur);
    cudaGetSymbolAddress((void**)&srcs, g_src);
    cudaGetSymbolAddress((void**)&bsum, g_bsum);
    cudaGetSymbolAddress((void**)&wimg, g_wimg);
    cudaGetSymbolAddress((void**)&mih,  g_mimg_h);
    cudaGetSymbolAddress((void**)&mil,  g_mimg_l);
    cudaGetSymbolAddress((void**)&xih,  g_ximg_h);
    cudaGetSymbolAddress((void**)&xil,  g_ximg_l);
    cudaGetSymbolAddress((void**)&yih,  g_yimg_h);
    cudaGetSymbolAddress((void**)&yil,  g_yimg_l);

    const int* src_arr = ei;
    const int* dst_arr = ei + E;

    // prep: weights (one launch) + x image
    prep_w_kernel<<<(6 * 16384 + 255) / 256, 256>>>(Wl1, Wr1, Wl2, Wr2, Wl3, Wr3, wimg);
    prep_x_kernel<<<(N * 32 + 255) / 256, 256>>>(x, xih, xil, N);

    // CSR build (parallel 3-phase scan)
    int nb = (N + 1023) / 1024;
    cudaMemsetAsync(cnt, 0, (size_t)N * sizeof(int));
    count_kernel<<<(E + 255) / 256, 256>>>(dst_arr, cnt, E);
    bsum_kernel<<<nb, 1024>>>(cnt, bsum, N);
    scan_bsum_kernel<<<1, 1024>>>(bsum, off, nb, N);
    scan_final_kernel<<<nb, 1024>>>(cnt, bsum, off, cur, N);
    fill_kernel<<<(E + 255) / 256, 256>>>(src_arr, dst_arr, cur, srcs, E);

    cudaFuncSetAttribute((const void*)gemm_mma_kernel,
                         cudaFuncAttributeMaxDynamicSharedMemorySize, SM_TOT);
    int gblocks = (N + 127) / 128;
    int ablocks = (N * 32 + 255) / 256;

    __half* im = wimg;
    // layer 1: A-h from x image, write y image
    agg_kernel<<<ablocks, 256>>>(x, mih, mil, off, srcs, N);
    gemm_mma_kernel<<<gblocks, GT, SM_TOT>>>(mih, mil, xih, xil, h0,
        im + 0 * 16384, im + 1 * 16384, b1, yih, yil, 1, N);
    // layer 2: A-h from y image, write x image
    agg_kernel<<<ablocks, 256>>>(h0, mih, mil, off, srcs, N);
    gemm_mma_kernel<<<gblocks, GT, SM_TOT>>>(mih, mil, yih, yil, h1,
        im + 2 * 16384, im + 3 * 16384, b2, xih, xil, 1, N);
    // layer 3: A-h from x image, no image write
    agg_kernel<<<ablocks, 256>>>(h1, mih, mil, off, srcs, N);
    gemm_mma_kernel<<<gblocks, GT, SM_TOT>>>(mih, mil, xih, xil, h0,
        im + 4 * 16384, im + 5 * 16384, b3, yih, yil, 0, N);

    // pooling + head
    pool_head_kernel<<<G, D>>>(h0, batch, Wro, bro, out, N);
}

// round 14
// speedup vs baseline: 1.5169x; 1.3290x over previous
#include <cuda_runtime.h>
#include <cuda_fp16.h>
#include <math.h>
#include <stdint.h>

#define D 128
#define MAXN 100000
#define MAXE 600000
#define NBLK 782   // ceil(MAXN/128)

// ---------------- static device scratch (no allocs allowed) ----------------
__device__ float g_h0[(size_t)MAXN * D];
__device__ float g_h1[(size_t)MAXN * D];
__device__ int   g_cnt[MAXN];
__device__ int   g_off[MAXN + 1];
__device__ int   g_cur[MAXN];
__device__ int   g_src[MAXE];
__device__ int   g_bsum[1024];
// 6 pre-swizzled fp16 weight images (3 layers x {Wl,Wr}), each 128k x 128n
__device__ __half g_wimg[6 * 16384];
// A-operand images (pre-swizzled fp16, per 128-row block: 2 k-halves x 16KB)
__device__ __half g_mimg[(size_t)NBLK * 16384];
__device__ __half g_ximg[(size_t)NBLK * 16384];
__device__ __half g_yimg[(size_t)NBLK * 16384];

// ---------------- helpers ----------------
__device__ __forceinline__ uint32_t smem_u32(const void* p) {
    uint32_t a;
    asm("{ .reg .u64 t; cvta.to.shared.u64 t, %1; cvt.u32.u64 %0, t; }" : "=r"(a) : "l"(p));
    return a;
}
__device__ __forceinline__ void cp16(uint32_t s, const void* g) {
    asm volatile("cp.async.cg.shared.global [%0], [%1], 16;" :: "r"(s), "l"(g));
}
__device__ __forceinline__ void ldsm_x4(uint32_t* r, uint32_t addr) {
    asm volatile("ldmatrix.sync.aligned.m8n8.x4.shared.b16 {%0,%1,%2,%3}, [%4];"
                 : "=r"(r[0]), "=r"(r[1]), "=r"(r[2]), "=r"(r[3]) : "r"(addr));
}
__device__ __forceinline__ void ldsm_x4_t(uint32_t* r, uint32_t addr) {
    asm volatile("ldmatrix.sync.aligned.m8n8.x4.trans.shared.b16 {%0,%1,%2,%3}, [%4];"
                 : "=r"(r[0]), "=r"(r[1]), "=r"(r[2]), "=r"(r[3]) : "r"(addr));
}
__device__ __forceinline__ void mma_f16(float* c, const uint32_t* a, const uint32_t* b) {
    asm volatile(
        "mma.sync.aligned.m16n8k16.row.col.f32.f16.f16.f32 "
        "{%0,%1,%2,%3}, {%4,%5,%6,%7}, {%8,%9}, {%0,%1,%2,%3};"
        : "+f"(c[0]), "+f"(c[1]), "+f"(c[2]), "+f"(c[3])
        : "r"(a[0]), "r"(a[1]), "r"(a[2]), "r"(a[3]), "r"(b[0]), "r"(b[1]));
}

// A-image byte offset: block, k-half, row (0..127), k within half (0..63)
__device__ __forceinline__ uint32_t a_img_byte(int b, int kh, int r, int kp) {
    return (uint32_t)b * 32768u + (uint32_t)kh * 16384u + (uint32_t)r * 128u
         + ((uint32_t)((kp >> 3) ^ (r & 7)) << 4) + ((uint32_t)(kp & 7) << 1);
}

// store 4 consecutive cols (col0 = 4*lane) of a node as fp16
__device__ __forceinline__ void store_a_quad(__half* img, int node, int lane, float4 v) {
    int b = node >> 7, r = node & 127;
    int col = lane << 2;
    uint32_t byte = a_img_byte(b, col >> 6, r, col & 63);
    __half2 p0 = __halves2half2(__float2half(v.x), __float2half(v.y));
    __half2 p1 = __halves2half2(__float2half(v.z), __float2half(v.w));
    char* p = (char*)img + byte;
    *(__half2*)(p)     = p0;
    *(__half2*)(p + 4) = p1;
}

// ---------------- CSR construction ----------------
__global__ void count_kernel(const int* __restrict__ dst, int* cnt, int E) {
    int e = blockIdx.x * blockDim.x + threadIdx.x;
    if (e < E) atomicAdd(&cnt[dst[e]], 1);
}

__global__ void bsum_kernel(const int* __restrict__ cnt, int* bsum, int N) {
    __shared__ int red[32];
    int i = blockIdx.x * 1024 + threadIdx.x;
    int v = (i < N) ? cnt[i] : 0;
#pragma unroll
    for (int o = 16; o > 0; o >>= 1) v += __shfl_down_sync(0xffffffff, v, o);
    if ((threadIdx.x & 31) == 0) red[threadIdx.x >> 5] = v;
    __syncthreads();
    if (threadIdx.x < 32) {
        int s = red[threadIdx.x];
#pragma unroll
        for (int o = 16; o > 0; o >>= 1) s += __shfl_down_sync(0xffffffff, s, o);
        if (threadIdx.x == 0) bsum[blockIdx.x] = s;
    }
}

__global__ void scan_bsum_kernel(int* bsum, int* off, int nb, int N) {
    __shared__ int s[1024];
    int t = threadIdx.x;
    int v = (t < nb) ? bsum[t] : 0;
    s[t] = v;
    __syncthreads();
    for (int d = 1; d < 1024; d <<= 1) {
        int x = (t >= d) ? s[t - d] : 0;
        __syncthreads();
        s[t] += x;
        __syncthreads();
    }
    if (t < nb) bsum[t] = s[t] - v;
    if (t == 1023) off[N] = s[1023];
}

__global__ void scan_final_kernel(const int* __restrict__ cnt, const int* __restrict__ bsum,
                                  int* off, int* cur, int N) {
    __shared__ int s[1024];
    int t = threadIdx.x;
    int i = blockIdx.x * 1024 + t;
    int v = (i < N) ? cnt[i] : 0;
    s[t] = v;
    __syncthreads();
    for (int d = 1; d < 1024; d <<= 1) {
        int x = (t >= d) ? s[t - d] : 0;
        __syncthreads();
        s[t] += x;
        __syncthreads();
    }
    if (i < N) {
        int excl = s[t] - v + bsum[blockIdx.x];
        off[i] = excl;
        cur[i] = excl;
    }
}

__global__ void fill_kernel(const int* __restrict__ src, const int* __restrict__ dst,
                            int* cur, int* out, int E) {
    int e = blockIdx.x * blockDim.x + threadIdx.x;
    if (e < E) {
        int d = dst[e];
        int pos = atomicAdd(&cur[d], 1);
        out[pos] = src[e];
    }
}

// ---------------- aggregation: warp-per-node CSR mean -> fp16 image --------
__global__ __launch_bounds__(256) void agg_kernel(
    const float* __restrict__ h, __half* __restrict__ img,
    const int* __restrict__ off, const int* __restrict__ srcs, int N)
{
    int gw = (blockIdx.x * 256 + threadIdx.x) >> 5;
    int lane = threadIdx.x & 31;
    if (gw >= N) return;

    int s = __ldg(&off[gw]);
    int e = __ldg(&off[gw + 1]);

    float4 acc = make_float4(0.f, 0.f, 0.f, 0.f);
    int k = s;
    for (; k + 4 <= e; k += 4) {
        int u0 = __ldg(&srcs[k]);
        int u1 = __ldg(&srcs[k + 1]);
        int u2 = __ldg(&srcs[k + 2]);
        int u3 = __ldg(&srcs[k + 3]);
        float4 a = __ldg((const float4*)(h + (size_t)u0 * D + lane * 4));
        float4 b = __ldg((const float4*)(h + (size_t)u1 * D + lane * 4));
        float4 c = __ldg((const float4*)(h + (size_t)u2 * D + lane * 4));
        float4 d = __ldg((const float4*)(h + (size_t)u3 * D + lane * 4));
        acc.x += (a.x + b.x) + (c.x + d.x);
        acc.y += (a.y + b.y) + (c.y + d.y);
        acc.z += (a.z + b.z) + (c.z + d.z);
        acc.w += (a.w + b.w) + (c.w + d.w);
    }
    for (; k < e; ++k) {
        int u = __ldg(&srcs[k]);
        float4 a = __ldg((const float4*)(h + (size_t)u * D + lane * 4));
        acc.x += a.x; acc.y += a.y; acc.z += a.z; acc.w += a.w;
    }
    float ic = 1.0f / (float)max(e - s, 1);
    acc.x *= ic; acc.y *= ic; acc.z *= ic; acc.w *= ic;
    store_a_quad(img, gw, lane, acc);
}

// ---------------- x -> fp16 image ----------------
__global__ void prep_x_kernel(const float* __restrict__ x,
                              __half* __restrict__ img, int N)
{
    int i = blockIdx.x * 256 + threadIdx.x;
    int node = i >> 5;
    int lane = i & 31;
    if (node >= N) return;
    float4 v = __ldg((const float4*)(x + (size_t)node * D + lane * 4));
    store_a_quad(img, node, lane, v);
}

// ---------------- weight prep (6 matrices, single fp16, one launch) --------
// Image layout (per k-chunk of 64): byte = (k>>6)*16384 + (k&63)*256
//                                        + (((n>>3) ^ (k&7)) << 4) + (n&7)*2
__global__ void prep_w_kernel(const float* W0, const float* W1, const float* W2,
                              const float* W3, const float* W4, const float* W5,
                              __half* __restrict__ wimg)
{
    int gi = blockIdx.x * 256 + threadIdx.x;
    if (gi >= 6 * 16384) return;
    int m = gi >> 14;
    int i = gi & 16383;
    const float* Ws[6] = {W0, W1, W2, W3, W4, W5};
    int k = i >> 7;
    int n = i & 127;
    float x = __ldg(Ws[m] + k * 128 + n);
    uint32_t byte = (uint32_t)(k >> 6) * 16384u + (uint32_t)(k & 63) * 256u
                  + ((uint32_t)((n >> 3) ^ (k & 7)) << 4) + (uint32_t)(n & 7) * 2u;
    __half* img = wimg + (size_t)m * 16384;
    img[byte >> 1] = __float2half(x);
}

// ---------------- HMMA GEMM: relu([mean|h] @ [Wl;Wr] + b), plain fp16 ------
// CTA: 128 rows x 128 cols, K=256 in 4 chunks of 64. 8 warps, warp = 32x64.
// Per k-step per warp: 8 HMMA.
#define GT 256
#define SM_A 0
#define SM_W 16384
#define SM_TOT 32768

__global__ __launch_bounds__(GT, 2) void gemm_mma_kernel(
    const __half* __restrict__ ma, const __half* __restrict__ ha,
    float* __restrict__ h_out,
    const __half* __restrict__ wl, const __half* __restrict__ wr,
    const float* __restrict__ bias,
    __half* __restrict__ oimg, int write_img, int N)
{
    extern __shared__ char smem[];
    const uint32_t sb = smem_u32(smem);
    const int t = threadIdx.x;
    const int lane = t & 31;
    const int w = t >> 5;
    const int wrow = (w & 3) * 32;
    const int wcol = (w >> 2) * 64;
    const int row0 = blockIdx.x * 128;

    const __half* as[2] = {ma, ha};
    const __half* ws[2] = {wl, wr};

    float C[64];
#pragma unroll
    for (int i = 0; i < 64; ++i) C[i] = 0.f;

    const int rsel = (lane & 7) + ((lane >> 3) & 1) * 8;
    const int usel = lane >> 4;

    for (int chunk = 0; chunk < 4; ++chunk) {
        const int mat = chunk >> 1;   // 0: mean@Wl, 1: h@Wr
        const int kh  = chunk & 1;

        // ---- stage A + W: 2 x 16KB pure cp.async copies ----
        const char* s2[2];
        s2[0] = (const char*)as[mat] + (size_t)blockIdx.x * 32768 + kh * 16384;
        s2[1] = (const char*)ws[mat] + kh * 16384;
        for (int i = t; i < 2048; i += GT) {
            int which = i >> 10;
            uint32_t o = (uint32_t)(i & 1023) << 4;
            cp16(sb + (uint32_t)which * 16384u + o, s2[which] + o);
        }
        asm volatile("cp.async.commit_group;" ::: "memory");
        asm volatile("cp.async.wait_group 0;" ::: "memory");
        __syncthreads();

        // ---- compute: 4 k-steps of 16; single sweep of 16 indep accumulators --
#pragma unroll
        for (int ks = 0; ks < 4; ++ks) {
            const int k0 = ks * 16;
            uint32_t af[2][4];
#pragma unroll
            for (int mf = 0; mf < 2; ++mf) {
                int row = wrow + mf * 16 + rsel;
                uint32_t unit = (uint32_t)(((k0 >> 3) + usel) ^ (lane & 7));
                ldsm_x4(af[mf], sb + SM_A + (uint32_t)row * 128u + (unit << 4));
            }
            uint32_t bf[4][4];
            const int krow = k0 + rsel;
#pragma unroll
            for (int nq = 0; nq < 4; ++nq) {
                const int n0 = wcol + nq * 16;
                uint32_t unit = (uint32_t)(((n0 >> 3) + usel) ^ (lane & 7));
                ldsm_x4_t(bf[nq], sb + SM_W + (uint32_t)krow * 256u + (unit << 4));
            }
#pragma unroll
            for (int nq = 0; nq < 4; ++nq)
#pragma unroll
                for (int mf = 0; mf < 2; ++mf) {
                    mma_f16(&C[((mf * 8 + nq * 2) << 2)],     af[mf], bf[nq]);
                    mma_f16(&C[((mf * 8 + nq * 2 + 1) << 2)], af[mf], bf[nq] + 2);
                }
        }
        __syncthreads();
    }

    // ---- epilogue: bias + relu + fp32 store + (optional) fp16 image store ----
#pragma unroll
    for (int mf = 0; mf < 2; ++mf) {
        int rloc = wrow + mf * 16 + (lane >> 2);
        int rlo = row0 + rloc;
#pragma unroll
        for (int nf = 0; nf < 8; ++nf) {
            int col = wcol + nf * 8 + (lane & 3) * 2;
            float b0 = __ldg(bias + col);
            float b1 = __ldg(bias + col + 1);
            const float* c = &C[((mf * 8 + nf) << 2)];
            float v0 = fmaxf(c[0] + b0, 0.f);
            float v1 = fmaxf(c[1] + b1, 0.f);
            float v2 = fmaxf(c[2] + b0, 0.f);
            float v3 = fmaxf(c[3] + b1, 0.f);
            if (rlo < N) {
                *(float2*)(h_out + (size_t)rlo * D + col) = make_float2(v0, v1);
                if (write_img) {
                    uint32_t byte = a_img_byte(blockIdx.x, col >> 6, rloc, col & 63);
                    *(__half2*)((char*)oimg + byte) =
                        __halves2half2(__float2half(v0), __float2half(v1));
                }
            }
            int rhi = rlo + 8;
            if (rhi < N) {
                *(float2*)(h_out + (size_t)rhi * D + col) = make_float2(v2, v3);
                if (write_img) {
                    uint32_t byte = a_img_byte(blockIdx.x, col >> 6, rloc + 8, col & 63);
                    *(__half2*)((char*)oimg + byte) =
                        __halves2half2(__float2half(v2), __float2half(v3));
                }
            }
        }
    }
}

// ---------------- pooled sum (sorted batch) + sigmoid head -----------------
__global__ void pool_head_kernel(const float* __restrict__ h, const int* __restrict__ batch,
                                 const float* __restrict__ Wro, const float* __restrict__ bro,
                                 float* __restrict__ out, int N)
{
    __shared__ int bounds[2];
    __shared__ float red[4];
    int g = blockIdx.x;
    int t = threadIdx.x;

    if (t < 2) {
        int target = g + t;
        int lo = 0, hi = N;
        while (lo < hi) {
            int mid = (lo + hi) >> 1;
            if (batch[mid] < target) lo = mid + 1; else hi = mid;
        }
        bounds[t] = lo;
    }
    __syncthreads();
    int s = bounds[0], e = bounds[1];

    float sum = 0.0f;
    for (int v = s; v < e; ++v) sum += h[(size_t)v * D + t];
    float val = sum * __ldg(&Wro[t]);
#pragma unroll
    for (int o = 16; o > 0; o >>= 1) val += __shfl_xor_sync(0xffffffff, val, o);
    if ((t & 31) == 0) red[t >> 5] = val;
    __syncthreads();
    if (t == 0) {
        float z = red[0] + red[1] + red[2] + red[3] + __ldg(bro);
        out[g] = 1.0f / (1.0f + expf(-z));
    }
}

// ---------------- launcher ----------------
extern "C" void kernel_launch(void* const* d_in, const int* in_sizes, int n_in,
                              void* d_out, int out_size)
{
    const float* x     = (const float*)d_in[0];
    const int*   ei    = (const int*)d_in[1];
    const int*   batch = (const int*)d_in[2];
    const float* Wl1 = (const float*)d_in[3];
    const float* Wr1 = (const float*)d_in[4];
    const float* b1  = (const float*)d_in[5];
    const float* Wl2 = (const float*)d_in[6];
    const float* Wr2 = (const float*)d_in[7];
    const float* b2  = (const float*)d_in[8];
    const float* Wl3 = (const float*)d_in[9];
    const float* Wr3 = (const float*)d_in[10];
    const float* b3  = (const float*)d_in[11];
    const float* Wro = (const float*)d_in[12];
    const float* bro = (const float*)d_in[13];
    float* out = (float*)d_out;

    int N = in_sizes[0] / D;
    int E = in_sizes[1] / 2;
    int G = out_size;

    float *h0, *h1;
    int *cnt, *off, *cur, *srcs, *bsum;
    __half *wimg, *mimg, *ximg, *yimg;
    cudaGetSymbolAddress((void**)&h0,   g_h0);
    cudaGetSymbolAddress((void**)&h1,   g_h1);
    cudaGetSymbolAddress((void**)&cnt,  g_cnt);
    cudaGetSymbolAddress((void**)&off,  g_off);
    cudaGetSymbolAddress((void**)&cur,  g_cur);
    cudaGetSymbolAddress((void**)&srcs, g_src);
    cudaGetSymbolAddress((void**)&bsum, g_bsum);
    cudaGetSymbolAddress((void**)&wimg, g_wimg);
    cudaGetSymbolAddress((void**)&mimg, g_mimg);
    cudaGetSymbolAddress((void**)&ximg, g_ximg);
    cudaGetSymbolAddress((void**)&yimg, g_yimg);

    const int* src_arr = ei;
    const int* dst_arr = ei + E;

    // prep: weights (one launch) + x image
    prep_w_kernel<<<(6 * 16384 + 255) / 256, 256>>>(Wl1, Wr1, Wl2, Wr2, Wl3, Wr3, wimg);
    prep_x_kernel<<<(N * 32 + 255) / 256, 256>>>(x, ximg, N);

    // CSR build (parallel 3-phase scan)
    int nb = (N + 1023) / 1024;
    cudaMemsetAsync(cnt, 0, (size_t)N * sizeof(int));
    count_kernel<<<(E + 255) / 256, 256>>>(dst_arr, cnt, E);
    bsum_kernel<<<nb, 1024>>>(cnt, bsum, N);
    scan_bsum_kernel<<<1, 1024>>>(bsum, off, nb, N);
    scan_final_kernel<<<nb, 1024>>>(cnt, bsum, off, cur, N);
    fill_kernel<<<(E + 255) / 256, 256>>>(src_arr, dst_arr, cur, srcs, E);

    cudaFuncSetAttribute((const void*)gemm_mma_kernel,
                         cudaFuncAttributeMaxDynamicSharedMemorySize, SM_TOT);
    int gblocks = (N + 127) / 128;
    int ablocks = (N * 32 + 255) / 256;

    __half* im = wimg;
    // layer 1: A-h from x image, write y image
    agg_kernel<<<ablocks, 256>>>(x, mimg, off, srcs, N);
    gemm_mma_kernel<<<gblocks, GT, SM_TOT>>>(mimg, ximg, h0,
        im + 0 * 16384, im + 1 * 16384, b1, yimg, 1, N);
    // layer 2: A-h from y image, write x image
    agg_kernel<<<ablocks, 256>>>(h0, mimg, off, srcs, N);
    gemm_mma_kernel<<<gblocks, GT, SM_TOT>>>(mimg, yimg, h1,
        im + 2 * 16384, im + 3 * 16384, b2, ximg, 1, N);
    // layer 3: A-h from x image, no image write
    agg_kernel<<<ablocks, 256>>>(h1, mimg, off, srcs, N);
    gemm_mma_kernel<<<gblocks, GT, SM_TOT>>>(mimg, ximg, h0,
        im + 4 * 16384, im + 5 * 16384, b3, yimg, 0, N);

    // pooling + head
    pool_head_kernel<<<G, D>>>(h0, batch, Wro, bro, out, N);
}

// round 15
// speedup vs baseline: 1.6678x; 1.0995x over previous
#include <cuda_runtime.h>
#include <cuda_fp16.h>
#include <math.h>
#include <stdint.h>

#define D 128
#define MAXN 100000
#define MAXE 600000
#define NBLK 782   // ceil(MAXN/128)

// ---------------- static device scratch (no allocs allowed) ----------------
__device__ float g_h0[(size_t)MAXN * D];
__device__ int   g_cnt[MAXN];
__device__ int   g_off[MAXN + 1];
__device__ int   g_cur[MAXN];
__device__ int   g_src[MAXE];
__device__ int   g_bsum[1024];
// 6 pre-swizzled fp16 weight images (3 layers x {Wl,Wr}), each 128k x 128n
__device__ __half g_wimg[6 * 16384];
// A-operand images (pre-swizzled fp16, per 128-row block: 2 k-halves x 16KB)
__device__ __half g_mimg[(size_t)NBLK * 16384];
__device__ __half g_ximg[(size_t)NBLK * 16384];
__device__ __half g_yimg[(size_t)NBLK * 16384];

// ---------------- helpers ----------------
__device__ __forceinline__ uint32_t smem_u32(const void* p) {
    uint32_t a;
    asm("{ .reg .u64 t; cvta.to.shared.u64 t, %1; cvt.u32.u64 %0, t; }" : "=r"(a) : "l"(p));
    return a;
}
__device__ __forceinline__ void cp16(uint32_t s, const void* g) {
    asm volatile("cp.async.cg.shared.global [%0], [%1], 16;" :: "r"(s), "l"(g));
}
__device__ __forceinline__ void ldsm_x4(uint32_t* r, uint32_t addr) {
    asm volatile("ldmatrix.sync.aligned.m8n8.x4.shared.b16 {%0,%1,%2,%3}, [%4];"
                 : "=r"(r[0]), "=r"(r[1]), "=r"(r[2]), "=r"(r[3]) : "r"(addr));
}
__device__ __forceinline__ void ldsm_x4_t(uint32_t* r, uint32_t addr) {
    asm volatile("ldmatrix.sync.aligned.m8n8.x4.trans.shared.b16 {%0,%1,%2,%3}, [%4];"
                 : "=r"(r[0]), "=r"(r[1]), "=r"(r[2]), "=r"(r[3]) : "r"(addr));
}
__device__ __forceinline__ void mma_f16(float* c, const uint32_t* a, const uint32_t* b) {
    asm volatile(
        "mma.sync.aligned.m16n8k16.row.col.f32.f16.f16.f32 "
        "{%0,%1,%2,%3}, {%4,%5,%6,%7}, {%8,%9}, {%0,%1,%2,%3};"
        : "+f"(c[0]), "+f"(c[1]), "+f"(c[2]), "+f"(c[3])
        : "r"(a[0]), "r"(a[1]), "r"(a[2]), "r"(a[3]), "r"(b[0]), "r"(b[1]));
}

// A-image byte offset: block, k-half, row (0..127), k within half (0..63)
__device__ __forceinline__ uint32_t a_img_byte(int b, int kh, int r, int kp) {
    return (uint32_t)b * 32768u + (uint32_t)kh * 16384u + (uint32_t)r * 128u
         + ((uint32_t)((kp >> 3) ^ (r & 7)) << 4) + ((uint32_t)(kp & 7) << 1);
}

// store 4 consecutive cols (col0 = 4*lane) of a node as fp16
__device__ __forceinline__ void store_a_quad(__half* img, int node, int lane, float4 v) {
    int b = node >> 7, r = node & 127;
    int col = lane << 2;
    uint32_t byte = a_img_byte(b, col >> 6, r, col & 63);
    __half2 p0 = __halves2half2(__float2half(v.x), __float2half(v.y));
    __half2 p1 = __halves2half2(__float2half(v.z), __float2half(v.w));
    char* p = (char*)img + byte;
    *(__half2*)(p)     = p0;
    *(__half2*)(p + 4) = p1;
}

// gather 4 consecutive cols (col0 = 4*lane) of a node from an fp16 image
__device__ __forceinline__ float4 load_a_quad(const __half* img, int node,
                                              int kh, uint32_t unit, uint32_t lodd) {
    int b = node >> 7, r = node & 127;
    uint32_t byte = (uint32_t)b * 32768u + (uint32_t)kh * 16384u + (uint32_t)r * 128u
                  + (((unit ^ (uint32_t)(r & 7)) << 4) | lodd);
    uint2 raw = __ldg((const uint2*)((const char*)img + byte));
    float2 f01 = __half22float2(*(__half2*)&raw.x);
    float2 f23 = __half22float2(*(__half2*)&raw.y);
    return make_float4(f01.x, f01.y, f23.x, f23.y);
}

// ---------------- CSR construction ----------------
__global__ void count_kernel(const int* __restrict__ dst, int* cnt, int E) {
    int e = blockIdx.x * blockDim.x + threadIdx.x;
    if (e < E) atomicAdd(&cnt[dst[e]], 1);
}

__global__ void bsum_kernel(const int* __restrict__ cnt, int* bsum, int N) {
    __shared__ int red[32];
    int i = blockIdx.x * 1024 + threadIdx.x;
    int v = (i < N) ? cnt[i] : 0;
#pragma unroll
    for (int o = 16; o > 0; o >>= 1) v += __shfl_down_sync(0xffffffff, v, o);
    if ((threadIdx.x & 31) == 0) red[threadIdx.x >> 5] = v;
    __syncthreads();
    if (threadIdx.x < 32) {
        int s = red[threadIdx.x];
#pragma unroll
        for (int o = 16; o > 0; o >>= 1) s += __shfl_down_sync(0xffffffff, s, o);
        if (threadIdx.x == 0) bsum[blockIdx.x] = s;
    }
}

__global__ void scan_bsum_kernel(int* bsum, int* off, int nb, int N) {
    __shared__ int s[1024];
    int t = threadIdx.x;
    int v = (t < nb) ? bsum[t] : 0;
    s[t] = v;
    __syncthreads();
    for (int d = 1; d < 1024; d <<= 1) {
        int x = (t >= d) ? s[t - d] : 0;
        __syncthreads();
        s[t] += x;
        __syncthreads();
    }
    if (t < nb) bsum[t] = s[t] - v;
    if (t == 1023) off[N] = s[1023];
}

__global__ void scan_final_kernel(const int* __restrict__ cnt, const int* __restrict__ bsum,
                                  int* off, int* cur, int N) {
    __shared__ int s[1024];
    int t = threadIdx.x;
    int i = blockIdx.x * 1024 + t;
    int v = (i < N) ? cnt[i] : 0;
    s[t] = v;
    __syncthreads();
    for (int d = 1; d < 1024; d <<= 1) {
        int x = (t >= d) ? s[t - d] : 0;
        __syncthreads();
        s[t] += x;
        __syncthreads();
    }
    if (i < N) {
        int excl = s[t] - v + bsum[blockIdx.x];
        off[i] = excl;
        cur[i] = excl;
    }
}

__global__ void fill_kernel(const int* __restrict__ src, const int* __restrict__ dst,
                            int* cur, int* out, int E) {
    int e = blockIdx.x * blockDim.x + threadIdx.x;
    if (e < E) {
        int d = dst[e];
        int pos = atomicAdd(&cur[d], 1);
        out[pos] = src[e];
    }
}

// ---------------- aggregation: warp-per-node CSR mean, fp16 image -> image --
__global__ __launch_bounds__(256) void agg_kernel(
    const __half* __restrict__ img_in, __half* __restrict__ img_out,
    const int* __restrict__ off, const int* __restrict__ srcs, int N)
{
    int gw = (blockIdx.x * 256 + threadIdx.x) >> 5;
    int lane = threadIdx.x & 31;
    if (gw >= N) return;

    const int kh = lane >> 4;
    const uint32_t unit = (uint32_t)((lane & 15) >> 1);
    const uint32_t lodd = (uint32_t)((lane & 1) << 3);

    int s = __ldg(&off[gw]);
    int e = __ldg(&off[gw + 1]);

    float4 acc = make_float4(0.f, 0.f, 0.f, 0.f);
    int k = s;
    for (; k + 4 <= e; k += 4) {
        int u0 = __ldg(&srcs[k]);
        int u1 = __ldg(&srcs[k + 1]);
        int u2 = __ldg(&srcs[k + 2]);
        int u3 = __ldg(&srcs[k + 3]);
        float4 a = load_a_quad(img_in, u0, kh, unit, lodd);
        float4 b = load_a_quad(img_in, u1, kh, unit, lodd);
        float4 c = load_a_quad(img_in, u2, kh, unit, lodd);
        float4 d = load_a_quad(img_in, u3, kh, unit, lodd);
        acc.x += (a.x + b.x) + (c.x + d.x);
        acc.y += (a.y + b.y) + (c.y + d.y);
        acc.z += (a.z + b.z) + (c.z + d.z);
        acc.w += (a.w + b.w) + (c.w + d.w);
    }
    for (; k < e; ++k) {
        int u = __ldg(&srcs[k]);
        float4 a = load_a_quad(img_in, u, kh, unit, lodd);
        acc.x += a.x; acc.y += a.y; acc.z += a.z; acc.w += a.w;
    }
    float ic = 1.0f / (float)max(e - s, 1);
    acc.x *= ic; acc.y *= ic; acc.z *= ic; acc.w *= ic;
    store_a_quad(img_out, gw, lane, acc);
}

// ---------------- x -> fp16 image ----------------
__global__ void prep_x_kernel(const float* __restrict__ x,
                              __half* __restrict__ img, int N)
{
    int i = blockIdx.x * 256 + threadIdx.x;
    int node = i >> 5;
    int lane = i & 31;
    if (node >= N) return;
    float4 v = __ldg((const float4*)(x + (size_t)node * D + lane * 4));
    store_a_quad(img, node, lane, v);
}

// ---------------- weight prep (6 matrices, single fp16, one launch) --------
__global__ void prep_w_kernel(const float* W0, const float* W1, const float* W2,
                              const float* W3, const float* W4, const float* W5,
                              __half* __restrict__ wimg)
{
    int gi = blockIdx.x * 256 + threadIdx.x;
    if (gi >= 6 * 16384) return;
    int m = gi >> 14;
    int i = gi & 16383;
    const float* Ws[6] = {W0, W1, W2, W3, W4, W5};
    int k = i >> 7;
    int n = i & 127;
    float x = __ldg(Ws[m] + k * 128 + n);
    uint32_t byte = (uint32_t)(k >> 6) * 16384u + (uint32_t)(k & 63) * 256u
                  + ((uint32_t)((n >> 3) ^ (k & 7)) << 4) + (uint32_t)(n & 7) * 2u;
    __half* img = wimg + (size_t)m * 16384;
    img[byte >> 1] = __float2half(x);
}

// ---------------- HMMA GEMM: relu([mean|h] @ [Wl;Wr] + b), plain fp16 ------
// CTA: 128 rows x 128 cols, K=256 in 4 chunks of 64. 8 warps, warp = 32x64.
#define GT 256
#define SM_A 0
#define SM_W 16384
#define SM_TOT 32768

__global__ __launch_bounds__(GT, 2) void gemm_mma_kernel(
    const __half* __restrict__ ma, const __half* __restrict__ ha,
    float* __restrict__ h_out,
    const __half* __restrict__ wl, const __half* __restrict__ wr,
    const float* __restrict__ bias,
    __half* __restrict__ oimg, int write_img, int write_f32, int N)
{
    extern __shared__ char smem[];
    const uint32_t sb = smem_u32(smem);
    const int t = threadIdx.x;
    const int lane = t & 31;
    const int w = t >> 5;
    const int wrow = (w & 3) * 32;
    const int wcol = (w >> 2) * 64;
    const int row0 = blockIdx.x * 128;

    const __half* as[2] = {ma, ha};
    const __half* ws[2] = {wl, wr};

    float C[64];
#pragma unroll
    for (int i = 0; i < 64; ++i) C[i] = 0.f;

    const int rsel = (lane & 7) + ((lane >> 3) & 1) * 8;
    const int usel = lane >> 4;

    for (int chunk = 0; chunk < 4; ++chunk) {
        const int mat = chunk >> 1;   // 0: mean@Wl, 1: h@Wr
        const int kh  = chunk & 1;

        // ---- stage A + W: 2 x 16KB pure cp.async copies ----
        const char* s2[2];
        s2[0] = (const char*)as[mat] + (size_t)blockIdx.x * 32768 + kh * 16384;
        s2[1] = (const char*)ws[mat] + kh * 16384;
        for (int i = t; i < 2048; i += GT) {
            int which = i >> 10;
            uint32_t o = (uint32_t)(i & 1023) << 4;
            cp16(sb + (uint32_t)which * 16384u + o, s2[which] + o);
        }
        asm volatile("cp.async.commit_group;" ::: "memory");
        asm volatile("cp.async.wait_group 0;" ::: "memory");
        __syncthreads();

        // ---- compute: 4 k-steps of 16; 16 independent accumulators --------
#pragma unroll
        for (int ks = 0; ks < 4; ++ks) {
            const int k0 = ks * 16;
            uint32_t af[2][4];
#pragma unroll
            for (int mf = 0; mf < 2; ++mf) {
                int row = wrow + mf * 16 + rsel;
                uint32_t unit = (uint32_t)(((k0 >> 3) + usel) ^ (lane & 7));
                ldsm_x4(af[mf], sb + SM_A + (uint32_t)row * 128u + (unit << 4));
            }
            uint32_t bf[4][4];
            const int krow = k0 + rsel;
#pragma unroll
            for (int nq = 0; nq < 4; ++nq) {
                const int n0 = wcol + nq * 16;
                uint32_t unit = (uint32_t)(((n0 >> 3) + usel) ^ (lane & 7));
                ldsm_x4_t(bf[nq], sb + SM_W + (uint32_t)krow * 256u + (unit << 4));
            }
#pragma unroll
            for (int nq = 0; nq < 4; ++nq)
#pragma unroll
                for (int mf = 0; mf < 2; ++mf) {
                    mma_f16(&C[((mf * 8 + nq * 2) << 2)],     af[mf], bf[nq]);
                    mma_f16(&C[((mf * 8 + nq * 2 + 1) << 2)], af[mf], bf[nq] + 2);
                }
        }
        __syncthreads();
    }

    // ---- epilogue: bias + relu + optional fp32 / fp16-image stores --------
#pragma unroll
    for (int mf = 0; mf < 2; ++mf) {
        int rloc = wrow + mf * 16 + (lane >> 2);
        int rlo = row0 + rloc;
#pragma unroll
        for (int nf = 0; nf < 8; ++nf) {
            int col = wcol + nf * 8 + (lane & 3) * 2;
            float b0 = __ldg(bias + col);
            float b1 = __ldg(bias + col + 1);
            const float* c = &C[((mf * 8 + nf) << 2)];
            float v0 = fmaxf(c[0] + b0, 0.f);
            float v1 = fmaxf(c[1] + b1, 0.f);
            float v2 = fmaxf(c[2] + b0, 0.f);
            float v3 = fmaxf(c[3] + b1, 0.f);
            if (rlo < N) {
                if (write_f32)
                    *(float2*)(h_out + (size_t)rlo * D + col) = make_float2(v0, v1);
                if (write_img) {
                    uint32_t byte = a_img_byte(blockIdx.x, col >> 6, rloc, col & 63);
                    *(__half2*)((char*)oimg + byte) =
                        __halves2half2(__float2half(v0), __float2half(v1));
                }
            }
            int rhi = rlo + 8;
            if (rhi < N) {
                if (write_f32)
                    *(float2*)(h_out + (size_t)rhi * D + col) = make_float2(v2, v3);
                if (write_img) {
                    uint32_t byte = a_img_byte(blockIdx.x, col >> 6, rloc + 8, col & 63);
                    *(__half2*)((char*)oimg + byte) =
                        __halves2half2(__float2half(v2), __float2half(v3));
                }
            }
        }
    }
}

// ---------------- pooled sum (sorted batch) + sigmoid head -----------------
__global__ void pool_head_kernel(const float* __restrict__ h, const int* __restrict__ batch,
                                 const float* __restrict__ Wro, const float* __restrict__ bro,
                                 float* __restrict__ out, int N)
{
    __shared__ int bounds[2];
    __shared__ float red[4];
    int g = blockIdx.x;
    int t = threadIdx.x;

    if (t < 2) {
        int target = g + t;
        int lo = 0, hi = N;
        while (lo < hi) {
            int mid = (lo + hi) >> 1;
            if (batch[mid] < target) lo = mid + 1; else hi = mid;
        }
        bounds[t] = lo;
    }
    __syncthreads();
    int s = bounds[0], e = bounds[1];

    float sum = 0.0f;
    for (int v = s; v < e; ++v) sum += h[(size_t)v * D + t];
    float val = sum * __ldg(&Wro[t]);
#pragma unroll
    for (int o = 16; o > 0; o >>= 1) val += __shfl_xor_sync(0xffffffff, val, o);
    if ((t & 31) == 0) red[t >> 5] = val;
    __syncthreads();
    if (t == 0) {
        float z = red[0] + red[1] + red[2] + red[3] + __ldg(bro);
        out[g] = 1.0f / (1.0f + expf(-z));
    }
}

// ---------------- launcher ----------------
extern "C" void kernel_launch(void* const* d_in, const int* in_sizes, int n_in,
                              void* d_out, int out_size)
{
    const float* x     = (const float*)d_in[0];
    const int*   ei    = (const int*)d_in[1];
    const int*   batch = (const int*)d_in[2];
    const float* Wl1 = (const float*)d_in[3];
    const float* Wr1 = (const float*)d_in[4];
    const float* b1  = (const float*)d_in[5];
    const float* Wl2 = (const float*)d_in[6];
    const float* Wr2 = (const float*)d_in[7];
    const float* b2  = (const float*)d_in[8];
    const float* Wl3 = (const float*)d_in[9];
    const float* Wr3 = (const float*)d_in[10];
    const float* b3  = (const float*)d_in[11];
    const float* Wro = (const float*)d_in[12];
    const float* bro = (const float*)d_in[13];
    float* out = (float*)d_out;

    int N = in_sizes[0] / D;
    int E = in_sizes[1] / 2;
    int G = out_size;

    float *h0;
    int *cnt, *off, *cur, *srcs, *bsum;
    __half *wimg, *mimg, *ximg, *yimg;
    cudaGetSymbolAddress((void**)&h0,   g_h0);
    cudaGetSymbolAddress((void**)&cnt,  g_cnt);
    cudaGetSymbolAddress((void**)&off,  g_off);
    cudaGetSymbolAddress((void**)&cur,  g_cur);
    cudaGetSymbolAddress((void**)&srcs, g_src);
    cudaGetSymbolAddress((void**)&bsum, g_bsum);
    cudaGetSymbolAddress((void**)&wimg, g_wimg);
    cudaGetSymbolAddress((void**)&mimg, g_mimg);
    cudaGetSymbolAddress((void**)&ximg, g_ximg);
    cudaGetSymbolAddress((void**)&yimg, g_yimg);

    const int* src_arr = ei;
    const int* dst_arr = ei + E;

    // prep: weights (one launch) + x image
    prep_w_kernel<<<(6 * 16384 + 255) / 256, 256>>>(Wl1, Wr1, Wl2, Wr2, Wl3, Wr3, wimg);
    prep_x_kernel<<<(N * 32 + 255) / 256, 256>>>(x, ximg, N);

    // CSR build (parallel 3-phase scan)
    int nb = (N + 1023) / 1024;
    cudaMemsetAsync(cnt, 0, (size_t)N * sizeof(int));
    count_kernel<<<(E + 255) / 256, 256>>>(dst_arr, cnt, E);
    bsum_kernel<<<nb, 1024>>>(cnt, bsum, N);
    scan_bsum_kernel<<<1, 1024>>>(bsum, off, nb, N);
    scan_final_kernel<<<nb, 1024>>>(cnt, bsum, off, cur, N);
    fill_kernel<<<(E + 255) / 256, 256>>>(src_arr, dst_arr, cur, srcs, E);

    cudaFuncSetAttribute((const void*)gemm_mma_kernel,
                         cudaFuncAttributeMaxDynamicSharedMemorySize, SM_TOT);
    int gblocks = (N + 127) / 128;
    int ablocks = (N * 32 + 255) / 256;

    __half* im = wimg;
    // layer 1: agg from x image, gemm -> y image only
    agg_kernel<<<ablocks, 256>>>(ximg, mimg, off, srcs, N);
    gemm_mma_kernel<<<gblocks, GT, SM_TOT>>>(mimg, ximg, h0,
        im + 0 * 16384, im + 1 * 16384, b1, yimg, 1, 0, N);
    // layer 2: agg from y image, gemm -> x image only (x image dead)
    agg_kernel<<<ablocks, 256>>>(yimg, mimg, off, srcs, N);
    gemm_mma_kernel<<<gblocks, GT, SM_TOT>>>(mimg, yimg, h0,
        im + 2 * 16384, im + 3 * 16384, b2, ximg, 1, 0, N);
    // layer 3: agg from x image, gemm -> fp32 h0 only (for pooling)
    agg_kernel<<<ablocks, 256>>>(ximg, mimg, off, srcs, N);
    gemm_mma_kernel<<<gblocks, GT, SM_TOT>>>(mimg, ximg, h0,
        im + 4 * 16384, im + 5 * 16384, b3, yimg, 0, 1, N);

    // pooling + head
    pool_head_kernel<<<G, D>>>(h0, batch, Wro, bro, out, N);
}

// round 16
// speedup vs baseline: 1.7285x; 1.0364x over previous
#include <cuda_runtime.h>
#include <cuda_fp16.h>
#include <math.h>
#include <stdint.h>

#define D 128
#define MAXN 100000
#define MAXE 600000
#define NBLK 782   // ceil(MAXN/128)

// ---------------- static device scratch (no allocs allowed) ----------------
__device__ int   g_cnt[MAXN];
__device__ int   g_off[MAXN + 1];
__device__ int   g_cur[MAXN];
__device__ int   g_src[MAXE];
__device__ int   g_bsum[1024];
// 6 pre-swizzled fp16 weight images (3 layers x {Wl,Wr}), each 128k x 128n
__device__ __half g_wimg[6 * 16384];
// A-operand images (pre-swizzled fp16, per 128-row block: 2 k-halves x 16KB)
__device__ __half g_mimg[(size_t)NBLK * 16384];
__device__ __half g_ximg[(size_t)NBLK * 16384];
__device__ __half g_yimg[(size_t)NBLK * 16384];

// ---------------- helpers ----------------
__device__ __forceinline__ uint32_t smem_u32(const void* p) {
    uint32_t a;
    asm("{ .reg .u64 t; cvta.to.shared.u64 t, %1; cvt.u32.u64 %0, t; }" : "=r"(a) : "l"(p));
    return a;
}
__device__ __forceinline__ void cp16(uint32_t s, const void* g) {
    asm volatile("cp.async.cg.shared.global [%0], [%1], 16;" :: "r"(s), "l"(g));
}
__device__ __forceinline__ void ldsm_x4(uint32_t* r, uint32_t addr) {
    asm volatile("ldmatrix.sync.aligned.m8n8.x4.shared.b16 {%0,%1,%2,%3}, [%4];"
                 : "=r"(r[0]), "=r"(r[1]), "=r"(r[2]), "=r"(r[3]) : "r"(addr));
}
__device__ __forceinline__ void ldsm_x4_t(uint32_t* r, uint32_t addr) {
    asm volatile("ldmatrix.sync.aligned.m8n8.x4.trans.shared.b16 {%0,%1,%2,%3}, [%4];"
                 : "=r"(r[0]), "=r"(r[1]), "=r"(r[2]), "=r"(r[3]) : "r"(addr));
}
__device__ __forceinline__ void mma_f16(float* c, const uint32_t* a, const uint32_t* b) {
    asm volatile(
        "mma.sync.aligned.m16n8k16.row.col.f32.f16.f16.f32 "
        "{%0,%1,%2,%3}, {%4,%5,%6,%7}, {%8,%9}, {%0,%1,%2,%3};"
        : "+f"(c[0]), "+f"(c[1]), "+f"(c[2]), "+f"(c[3])
        : "r"(a[0]), "r"(a[1]), "r"(a[2]), "r"(a[3]), "r"(b[0]), "r"(b[1]));
}

// A-image byte offset: block, k-half, row (0..127), k within half (0..63)
__device__ __forceinline__ uint32_t a_img_byte(int b, int kh, int r, int kp) {
    return (uint32_t)b * 32768u + (uint32_t)kh * 16384u + (uint32_t)r * 128u
         + ((uint32_t)((kp >> 3) ^ (r & 7)) << 4) + ((uint32_t)(kp & 7) << 1);
}

// store 4 consecutive cols (col0 = 4*lane) of a node as fp16
__device__ __forceinline__ void store_a_quad(__half* img, int node, int lane, float4 v) {
    int b = node >> 7, r = node & 127;
    int col = lane << 2;
    uint32_t byte = a_img_byte(b, col >> 6, r, col & 63);
    __half2 p0 = __halves2half2(__float2half(v.x), __float2half(v.y));
    __half2 p1 = __halves2half2(__float2half(v.z), __float2half(v.w));
    char* p = (char*)img + byte;
    *(__half2*)(p)     = p0;
    *(__half2*)(p + 4) = p1;
}

// gather 4 consecutive cols (col0 = 4*lane) of a node from an fp16 image
__device__ __forceinline__ float4 load_a_quad(const __half* img, int node,
                                              int kh, uint32_t unit, uint32_t lodd) {
    int b = node >> 7, r = node & 127;
    uint32_t byte = (uint32_t)b * 32768u + (uint32_t)kh * 16384u + (uint32_t)r * 128u
                  + (((unit ^ (uint32_t)(r & 7)) << 4) | lodd);
    uint2 raw = __ldg((const uint2*)((const char*)img + byte));
    float2 f01 = __half22float2(*(__half2*)&raw.x);
    float2 f23 = __half22float2(*(__half2*)&raw.y);
    return make_float4(f01.x, f01.y, f23.x, f23.y);
}

// ---------------- CSR construction ----------------
__global__ void count_kernel(const int* __restrict__ dst, int* cnt, int E) {
    int e = blockIdx.x * blockDim.x + threadIdx.x;
    if (e < E) atomicAdd(&cnt[dst[e]], 1);
}

__global__ void bsum_kernel(const int* __restrict__ cnt, int* bsum, int N) {
    __shared__ int red[32];
    int i = blockIdx.x * 1024 + threadIdx.x;
    int v = (i < N) ? cnt[i] : 0;
#pragma unroll
    for (int o = 16; o > 0; o >>= 1) v += __shfl_down_sync(0xffffffff, v, o);
    if ((threadIdx.x & 31) == 0) red[threadIdx.x >> 5] = v;
    __syncthreads();
    if (threadIdx.x < 32) {
        int s = red[threadIdx.x];
#pragma unroll
        for (int o = 16; o > 0; o >>= 1) s += __shfl_down_sync(0xffffffff, s, o);
        if (threadIdx.x == 0) bsum[blockIdx.x] = s;
    }
}

__global__ void scan_bsum_kernel(int* bsum, int* off, int nb, int N) {
    __shared__ int s[1024];
    int t = threadIdx.x;
    int v = (t < nb) ? bsum[t] : 0;
    s[t] = v;
    __syncthreads();
    for (int d = 1; d < 1024; d <<= 1) {
        int x = (t >= d) ? s[t - d] : 0;
        __syncthreads();
        s[t] += x;
        __syncthreads();
    }
    if (t < nb) bsum[t] = s[t] - v;
    if (t == 1023) off[N] = s[1023];
}

__global__ void scan_final_kernel(const int* __restrict__ cnt, const int* __restrict__ bsum,
                                  int* off, int* cur, int N) {
    __shared__ int s[1024];
    int t = threadIdx.x;
    int i = blockIdx.x * 1024 + t;
    int v = (i < N) ? cnt[i] : 0;
    s[t] = v;
    __syncthreads();
    for (int d = 1; d < 1024; d <<= 1) {
        int x = (t >= d) ? s[t - d] : 0;
        __syncthreads();
        s[t] += x;
        __syncthreads();
    }
    if (i < N) {
        int excl = s[t] - v + bsum[blockIdx.x];
        off[i] = excl;
        cur[i] = excl;
    }
}

__global__ void fill_kernel(const int* __restrict__ src, const int* __restrict__ dst,
                            int* cur, int* out, int E) {
    int e = blockIdx.x * blockDim.x + threadIdx.x;
    if (e < E) {
        int d = dst[e];
        int pos = atomicAdd(&cur[d], 1);
        out[pos] = src[e];
    }
}

// ---------------- aggregation: warp-per-node CSR mean, fp16 image -> image --
__global__ __launch_bounds__(256) void agg_kernel(
    const __half* __restrict__ img_in, __half* __restrict__ img_out,
    const int* __restrict__ off, const int* __restrict__ srcs, int N)
{
    int gw = (blockIdx.x * 256 + threadIdx.x) >> 5;
    int lane = threadIdx.x & 31;
    if (gw >= N) return;

    const int kh = lane >> 4;
    const uint32_t unit = (uint32_t)((lane & 15) >> 1);
    const uint32_t lodd = (uint32_t)((lane & 1) << 3);

    int s = __ldg(&off[gw]);
    int e = __ldg(&off[gw + 1]);

    float4 acc = make_float4(0.f, 0.f, 0.f, 0.f);
    int k = s;
    for (; k + 4 <= e; k += 4) {
        int u0 = __ldg(&srcs[k]);
        int u1 = __ldg(&srcs[k + 1]);
        int u2 = __ldg(&srcs[k + 2]);
        int u3 = __ldg(&srcs[k + 3]);
        float4 a = load_a_quad(img_in, u0, kh, unit, lodd);
        float4 b = load_a_quad(img_in, u1, kh, unit, lodd);
        float4 c = load_a_quad(img_in, u2, kh, unit, lodd);
        float4 d = load_a_quad(img_in, u3, kh, unit, lodd);
        acc.x += (a.x + b.x) + (c.x + d.x);
        acc.y += (a.y + b.y) + (c.y + d.y);
        acc.z += (a.z + b.z) + (c.z + d.z);
        acc.w += (a.w + b.w) + (c.w + d.w);
    }
    for (; k < e; ++k) {
        int u = __ldg(&srcs[k]);
        float4 a = load_a_quad(img_in, u, kh, unit, lodd);
        acc.x += a.x; acc.y += a.y; acc.z += a.z; acc.w += a.w;
    }
    float ic = 1.0f / (float)max(e - s, 1);
    acc.x *= ic; acc.y *= ic; acc.z *= ic; acc.w *= ic;
    store_a_quad(img_out, gw, lane, acc);
}

// ---------------- x -> fp16 image ----------------
__global__ void prep_x_kernel(const float* __restrict__ x,
                              __half* __restrict__ img, int N)
{
    int i = blockIdx.x * 256 + threadIdx.x;
    int node = i >> 5;
    int lane = i & 31;
    if (node >= N) return;
    float4 v = __ldg((const float4*)(x + (size_t)node * D + lane * 4));
    store_a_quad(img, node, lane, v);
}

// ---------------- weight prep (6 matrices, single fp16, one launch) --------
__global__ void prep_w_kernel(const float* W0, const float* W1, const float* W2,
                              const float* W3, const float* W4, const float* W5,
                              __half* __restrict__ wimg)
{
    int gi = blockIdx.x * 256 + threadIdx.x;
    if (gi >= 6 * 16384) return;
    int m = gi >> 14;
    int i = gi & 16383;
    const float* Ws[6] = {W0, W1, W2, W3, W4, W5};
    int k = i >> 7;
    int n = i & 127;
    float x = __ldg(Ws[m] + k * 128 + n);
    uint32_t byte = (uint32_t)(k >> 6) * 16384u + (uint32_t)(k & 63) * 256u
                  + ((uint32_t)((n >> 3) ^ (k & 7)) << 4) + (uint32_t)(n & 7) * 2u;
    __half* img = wimg + (size_t)m * 16384;
    img[byte >> 1] = __float2half(x);
}

// ---------------- HMMA GEMM: relu([mean|h] @ [Wl;Wr] + b), plain fp16 ------
// CTA: 128 rows x 128 cols, K=256 in 4 chunks of 64. 8 warps, warp = 32x64.
// Output goes ONLY to the fp16 image (all layers).
#define GT 256
#define SM_A 0
#define SM_W 16384
#define SM_TOT 32768

__global__ __launch_bounds__(GT, 2) void gemm_mma_kernel(
    const __half* __restrict__ ma, const __half* __restrict__ ha,
    const __half* __restrict__ wl, const __half* __restrict__ wr,
    const float* __restrict__ bias,
    __half* __restrict__ oimg, int N)
{
    extern __shared__ char smem[];
    const uint32_t sb = smem_u32(smem);
    const int t = threadIdx.x;
    const int lane = t & 31;
    const int w = t >> 5;
    const int wrow = (w & 3) * 32;
    const int wcol = (w >> 2) * 64;
    const int row0 = blockIdx.x * 128;

    const __half* as[2] = {ma, ha};
    const __half* ws[2] = {wl, wr};

    float C[64];
#pragma unroll
    for (int i = 0; i < 64; ++i) C[i] = 0.f;

    const int rsel = (lane & 7) + ((lane >> 3) & 1) * 8;
    const int usel = lane >> 4;

    for (int chunk = 0; chunk < 4; ++chunk) {
        const int mat = chunk >> 1;   // 0: mean@Wl, 1: h@Wr
        const int kh  = chunk & 1;

        // ---- stage A + W: 2 x 16KB pure cp.async copies ----
        const char* s2[2];
        s2[0] = (const char*)as[mat] + (size_t)blockIdx.x * 32768 + kh * 16384;
        s2[1] = (const char*)ws[mat] + kh * 16384;
        for (int i = t; i < 2048; i += GT) {
            int which = i >> 10;
            uint32_t o = (uint32_t)(i & 1023) << 4;
            cp16(sb + (uint32_t)which * 16384u + o, s2[which] + o);
        }
        asm volatile("cp.async.commit_group;" ::: "memory");
        asm volatile("cp.async.wait_group 0;" ::: "memory");
        __syncthreads();

        // ---- compute: 4 k-steps of 16; 16 independent accumulators --------
#pragma unroll
        for (int ks = 0; ks < 4; ++ks) {
            const int k0 = ks * 16;
            uint32_t af[2][4];
#pragma unroll
            for (int mf = 0; mf < 2; ++mf) {
                int row = wrow + mf * 16 + rsel;
                uint32_t unit = (uint32_t)(((k0 >> 3) + usel) ^ (lane & 7));
                ldsm_x4(af[mf], sb + SM_A + (uint32_t)row * 128u + (unit << 4));
            }
            uint32_t bf[4][4];
            const int krow = k0 + rsel;
#pragma unroll
            for (int nq = 0; nq < 4; ++nq) {
                const int n0 = wcol + nq * 16;
                uint32_t unit = (uint32_t)(((n0 >> 3) + usel) ^ (lane & 7));
                ldsm_x4_t(bf[nq], sb + SM_W + (uint32_t)krow * 256u + (unit << 4));
            }
#pragma unroll
            for (int nq = 0; nq < 4; ++nq)
#pragma unroll
                for (int mf = 0; mf < 2; ++mf) {
                    mma_f16(&C[((mf * 8 + nq * 2) << 2)],     af[mf], bf[nq]);
                    mma_f16(&C[((mf * 8 + nq * 2 + 1) << 2)], af[mf], bf[nq] + 2);
                }
        }
        __syncthreads();
    }

    // ---- epilogue: bias + relu -> fp16 image ----
#pragma unroll
    for (int mf = 0; mf < 2; ++mf) {
        int rloc = wrow + mf * 16 + (lane >> 2);
        int rlo = row0 + rloc;
#pragma unroll
        for (int nf = 0; nf < 8; ++nf) {
            int col = wcol + nf * 8 + (lane & 3) * 2;
            float b0 = __ldg(bias + col);
            float b1 = __ldg(bias + col + 1);
            const float* c = &C[((mf * 8 + nf) << 2)];
            float v0 = fmaxf(c[0] + b0, 0.f);
            float v1 = fmaxf(c[1] + b1, 0.f);
            float v2 = fmaxf(c[2] + b0, 0.f);
            float v3 = fmaxf(c[3] + b1, 0.f);
            if (rlo < N) {
                uint32_t byte = a_img_byte(blockIdx.x, col >> 6, rloc, col & 63);
                *(__half2*)((char*)oimg + byte) =
                    __halves2half2(__float2half(v0), __float2half(v1));
            }
            int rhi = rlo + 8;
            if (rhi < N) {
                uint32_t byte = a_img_byte(blockIdx.x, col >> 6, rloc + 8, col & 63);
                *(__half2*)((char*)oimg + byte) =
                    __halves2half2(__float2half(v2), __float2half(v3));
            }
        }
    }
}

// ---------------- pooled sum (sorted batch) from fp16 image + sigmoid head --
__global__ void pool_head_kernel(const __half* __restrict__ img,
                                 const int* __restrict__ batch,
                                 const float* __restrict__ Wro, const float* __restrict__ bro,
                                 float* __restrict__ out, int N)
{
    __shared__ int bounds[2];
    __shared__ float red[4];
    int g = blockIdx.x;
    int t = threadIdx.x;   // t = feature column 0..127

    if (t < 2) {
        int target = g + t;
        int lo = 0, hi = N;
        while (lo < hi) {
            int mid = (lo + hi) >> 1;
            if (batch[mid] < target) lo = mid + 1; else hi = mid;
        }
        bounds[t] = lo;
    }
    __syncthreads();
    int s = bounds[0], e = bounds[1];

    const int kh = t >> 6;
    const int kp = t & 63;
    const uint32_t ubase = (uint32_t)(kp >> 3);
    const uint32_t lodd  = (uint32_t)(kp & 7) << 1;

    float sum = 0.0f;
    for (int v = s; v < e; ++v) {
        int b = v >> 7, r = v & 127;
        uint32_t byte = (uint32_t)b * 32768u + (uint32_t)kh * 16384u
                      + (uint32_t)r * 128u
                      + ((ubase ^ (uint32_t)(r & 7)) << 4) + lodd;
        sum += __half2float(*(const __half*)((const char*)img + byte));
    }
    float val = sum * __ldg(&Wro[t]);
#pragma unroll
    for (int o = 16; o > 0; o >>= 1) val += __shfl_xor_sync(0xffffffff, val, o);
    if ((t & 31) == 0) red[t >> 5] = val;
    __syncthreads();
    if (t == 0) {
        float z = red[0] + red[1] + red[2] + red[3] + __ldg(bro);
        out[g] = 1.0f / (1.0f + expf(-z));
    }
}

// ---------------- launcher ----------------
extern "C" void kernel_launch(void* const* d_in, const int* in_sizes, int n_in,
                              void* d_out, int out_size)
{
    const float* x     = (const float*)d_in[0];
    const int*   ei    = (const int*)d_in[1];
    const int*   batch = (const int*)d_in[2];
    const float* Wl1 = (const float*)d_in[3];
    const float* Wr1 = (const float*)d_in[4];
    const float* b1  = (const float*)d_in[5];
    const float* Wl2 = (const float*)d_in[6];
    const float* Wr2 = (const float*)d_in[7];
    const float* b2  = (const float*)d_in[8];
    const float* Wl3 = (const float*)d_in[9];
    const float* Wr3 = (const float*)d_in[10];
    const float* b3  = (const float*)d_in[11];
    const float* Wro = (const float*)d_in[12];
    const float* bro = (const float*)d_in[13];
    float* out = (float*)d_out;

    int N = in_sizes[0] / D;
    int E = in_sizes[1] / 2;
    int G = out_size;

    int *cnt, *off, *cur, *srcs, *bsum;
    __half *wimg, *mimg, *ximg, *yimg;
    cudaGetSymbolAddress((void**)&cnt,  g_cnt);
    cudaGetSymbolAddress((void**)&off,  g_off);
    cudaGetSymbolAddress((void**)&cur,  g_cur);
    cudaGetSymbolAddress((void**)&srcs, g_src);
    cudaGetSymbolAddress((void**)&bsum, g_bsum);
    cudaGetSymbolAddress((void**)&wimg, g_wimg);
    cudaGetSymbolAddress((void**)&mimg, g_mimg);
    cudaGetSymbolAddress((void**)&ximg, g_ximg);
    cudaGetSymbolAddress((void**)&yimg, g_yimg);

    const int* src_arr = ei;
    const int* dst_arr = ei + E;

    // prep: weights (one launch) + x image
    prep_w_kernel<<<(6 * 16384 + 255) / 256, 256>>>(Wl1, Wr1, Wl2, Wr2, Wl3, Wr3, wimg);
    prep_x_kernel<<<(N * 32 + 255) / 256, 256>>>(x, ximg, N);

    // CSR build (parallel 3-phase scan)
    int nb = (N + 1023) / 1024;
    cudaMemsetAsync(cnt, 0, (size_t)N * sizeof(int));
    count_kernel<<<(E + 255) / 256, 256>>>(dst_arr, cnt, E);
    bsum_kernel<<<nb, 1024>>>(cnt, bsum, N);
    scan_bsum_kernel<<<1, 1024>>>(bsum, off, nb, N);
    scan_final_kernel<<<nb, 1024>>>(cnt, bsum, off, cur, N);
    fill_kernel<<<(E + 255) / 256, 256>>>(src_arr, dst_arr, cur, srcs, E);

    cudaFuncSetAttribute((const void*)gemm_mma_kernel,
                         cudaFuncAttributeMaxDynamicSharedMemorySize, SM_TOT);
    int gblocks = (N + 127) / 128;
    int ablocks = (N * 32 + 255) / 256;

    __half* im = wimg;
    // layer 1: agg from x image, gemm -> y image
    agg_kernel<<<ablocks, 256>>>(ximg, mimg, off, srcs, N);
    gemm_mma_kernel<<<gblocks, GT, SM_TOT>>>(mimg, ximg,
        im + 0 * 16384, im + 1 * 16384, b1, yimg, N);
    // layer 2: agg from y image, gemm -> x image
    agg_kernel<<<ablocks, 256>>>(yimg, mimg, off, srcs, N);
    gemm_mma_kernel<<<gblocks, GT, SM_TOT>>>(mimg, yimg,
        im + 2 * 16384, im + 3 * 16384, b2, ximg, N);
    // layer 3: agg from x image, gemm -> y image
    agg_kernel<<<ablocks, 256>>>(ximg, mimg, off, srcs, N);
    gemm_mma_kernel<<<gblocks, GT, SM_TOT>>>(mimg, ximg,
        im + 4 * 16384, im + 5 * 16384, b3, yimg, N);

    // pooling + head (reads fp16 image)
    pool_head_kernel<<<G, D>>>(yimg, batch, Wro, bro, out, N);
}

// round 17
// speedup vs baseline: 1.7522x; 1.0137x over previous
#include <cuda_runtime.h>
#include <cuda_fp16.h>
#include <math.h>
#include <stdint.h>

#define D 128
#define MAXN 100000
#define MAXE 600000
#define NBLK 782   // ceil(MAXN/128)

// ---------------- static device scratch (no allocs allowed) ----------------
__device__ int   g_cnt[MAXN];
__device__ int   g_off[MAXN + 1];
__device__ int   g_cur[MAXN];
__device__ int   g_src[MAXE];
__device__ int   g_bsum[1024];
// 6 pre-swizzled fp16 weight images (3 layers x {Wl,Wr}), each 128k x 128n
__device__ __half g_wimg[6 * 16384];
// A-operand images (pre-swizzled fp16, per 128-row block: 2 k-halves x 16KB)
__device__ __half g_mimg[(size_t)NBLK * 16384];
__device__ __half g_ximg[(size_t)NBLK * 16384];
__device__ __half g_yimg[(size_t)NBLK * 16384];

// ---------------- helpers ----------------
__device__ __forceinline__ uint32_t smem_u32(const void* p) {
    uint32_t a;
    asm("{ .reg .u64 t; cvta.to.shared.u64 t, %1; cvt.u32.u64 %0, t; }" : "=r"(a) : "l"(p));
    return a;
}
__device__ __forceinline__ void cp16(uint32_t s, const void* g) {
    asm volatile("cp.async.cg.shared.global [%0], [%1], 16;" :: "r"(s), "l"(g));
}
__device__ __forceinline__ void ldsm_x4(uint32_t* r, uint32_t addr) {
    asm volatile("ldmatrix.sync.aligned.m8n8.x4.shared.b16 {%0,%1,%2,%3}, [%4];"
                 : "=r"(r[0]), "=r"(r[1]), "=r"(r[2]), "=r"(r[3]) : "r"(addr));
}
__device__ __forceinline__ void ldsm_x4_t(uint32_t* r, uint32_t addr) {
    asm volatile("ldmatrix.sync.aligned.m8n8.x4.trans.shared.b16 {%0,%1,%2,%3}, [%4];"
                 : "=r"(r[0]), "=r"(r[1]), "=r"(r[2]), "=r"(r[3]) : "r"(addr));
}
__device__ __forceinline__ void mma_f16(float* c, const uint32_t* a, const uint32_t* b) {
    asm volatile(
        "mma.sync.aligned.m16n8k16.row.col.f32.f16.f16.f32 "
        "{%0,%1,%2,%3}, {%4,%5,%6,%7}, {%8,%9}, {%0,%1,%2,%3};"
        : "+f"(c[0]), "+f"(c[1]), "+f"(c[2]), "+f"(c[3])
        : "r"(a[0]), "r"(a[1]), "r"(a[2]), "r"(a[3]), "r"(b[0]), "r"(b[1]));
}

// A-image byte offset: block, k-half, row (0..127), k within half (0..63)
__device__ __forceinline__ uint32_t a_img_byte(int b, int kh, int r, int kp) {
    return (uint32_t)b * 32768u + (uint32_t)kh * 16384u + (uint32_t)r * 128u
         + ((uint32_t)((kp >> 3) ^ (r & 7)) << 4) + ((uint32_t)(kp & 7) << 1);
}

// store 4 consecutive cols (col0 = 4*lane) of a node as fp16
__device__ __forceinline__ void store_a_quad(__half* img, int node, int lane, float4 v) {
    int b = node >> 7, r = node & 127;
    int col = lane << 2;
    uint32_t byte = a_img_byte(b, col >> 6, r, col & 63);
    __half2 p0 = __halves2half2(__float2half(v.x), __float2half(v.y));
    __half2 p1 = __halves2half2(__float2half(v.z), __float2half(v.w));
    char* p = (char*)img + byte;
    *(__half2*)(p)     = p0;
    *(__half2*)(p + 4) = p1;
}

// gather 4 consecutive cols (col0 = 4*lane) of a node from an fp16 image
__device__ __forceinline__ float4 load_a_quad(const __half* img, int node,
                                              int kh, uint32_t unit, uint32_t lodd) {
    int b = node >> 7, r = node & 127;
    uint32_t byte = (uint32_t)b * 32768u + (uint32_t)kh * 16384u + (uint32_t)r * 128u
                  + (((unit ^ (uint32_t)(r & 7)) << 4) | lodd);
    uint2 raw = __ldg((const uint2*)((const char*)img + byte));
    float2 f01 = __half22float2(*(__half2*)&raw.x);
    float2 f23 = __half22float2(*(__half2*)&raw.y);
    return make_float4(f01.x, f01.y, f23.x, f23.y);
}

// ---------------- CSR construction ----------------
__global__ void count_kernel(const int* __restrict__ dst, int* cnt, int E) {
    int e = blockIdx.x * blockDim.x + threadIdx.x;
    if (e < E) atomicAdd(&cnt[dst[e]], 1);
}

__global__ void bsum_kernel(const int* __restrict__ cnt, int* bsum, int N) {
    __shared__ int red[32];
    int i = blockIdx.x * 1024 + threadIdx.x;
    int v = (i < N) ? cnt[i] : 0;
#pragma unroll
    for (int o = 16; o > 0; o >>= 1) v += __shfl_down_sync(0xffffffff, v, o);
    if ((threadIdx.x & 31) == 0) red[threadIdx.x >> 5] = v;
    __syncthreads();
    if (threadIdx.x < 32) {
        int s = red[threadIdx.x];
#pragma unroll
        for (int o = 16; o > 0; o >>= 1) s += __shfl_down_sync(0xffffffff, s, o);
        if (threadIdx.x == 0) bsum[blockIdx.x] = s;
    }
}

__global__ void scan_bsum_kernel(int* bsum, int* off, int nb, int N) {
    __shared__ int s[1024];
    int t = threadIdx.x;
    int v = (t < nb) ? bsum[t] : 0;
    s[t] = v;
    __syncthreads();
    for (int d = 1; d < 1024; d <<= 1) {
        int x = (t >= d) ? s[t - d] : 0;
        __syncthreads();
        s[t] += x;
        __syncthreads();
    }
    if (t < nb) bsum[t] = s[t] - v;
    if (t == 1023) off[N] = s[1023];
}

__global__ void scan_final_kernel(const int* __restrict__ cnt, const int* __restrict__ bsum,
                                  int* off, int* cur, int N) {
    __shared__ int s[1024];
    int t = threadIdx.x;
    int i = blockIdx.x * 1024 + t;
    int v = (i < N) ? cnt[i] : 0;
    s[t] = v;
    __syncthreads();
    for (int d = 1; d < 1024; d <<= 1) {
        int x = (t >= d) ? s[t - d] : 0;
        __syncthreads();
        s[t] += x;
        __syncthreads();
    }
    if (i < N) {
        int excl = s[t] - v + bsum[blockIdx.x];
        off[i] = excl;
        cur[i] = excl;
    }
}

__global__ void fill_kernel(const int* __restrict__ src, const int* __restrict__ dst,
                            int* cur, int* out, int E) {
    int e = blockIdx.x * blockDim.x + threadIdx.x;
    if (e < E) {
        int d = dst[e];
        int pos = atomicAdd(&cur[d], 1);
        out[pos] = src[e];
    }
}

// ---------------- aggregation: warp-per-node CSR mean, fp16 image -> image --
__global__ __launch_bounds__(256) void agg_kernel(
    const __half* __restrict__ img_in, __half* __restrict__ img_out,
    const int* __restrict__ off, const int* __restrict__ srcs, int N)
{
    int gw = (blockIdx.x * 256 + threadIdx.x) >> 5;
    int lane = threadIdx.x & 31;
    if (gw >= N) return;

    const int kh = lane >> 4;
    const uint32_t unit = (uint32_t)((lane & 15) >> 1);
    const uint32_t lodd = (uint32_t)((lane & 1) << 3);

    int s = __ldg(&off[gw]);
    int e = __ldg(&off[gw + 1]);

    float4 acc = make_float4(0.f, 0.f, 0.f, 0.f);
    int k = s;
    for (; k + 4 <= e; k += 4) {
        int u0 = __ldg(&srcs[k]);
        int u1 = __ldg(&srcs[k + 1]);
        int u2 = __ldg(&srcs[k + 2]);
        int u3 = __ldg(&srcs[k + 3]);
        float4 a = load_a_quad(img_in, u0, kh, unit, lodd);
        float4 b = load_a_quad(img_in, u1, kh, unit, lodd);
        float4 c = load_a_quad(img_in, u2, kh, unit, lodd);
        float4 d = load_a_quad(img_in, u3, kh, unit, lodd);
        acc.x += (a.x + b.x) + (c.x + d.x);
        acc.y += (a.y + b.y) + (c.y + d.y);
        acc.z += (a.z + b.z) + (c.z + d.z);
        acc.w += (a.w + b.w) + (c.w + d.w);
    }
    for (; k < e; ++k) {
        int u = __ldg(&srcs[k]);
        float4 a = load_a_quad(img_in, u, kh, unit, lodd);
        acc.x += a.x; acc.y += a.y; acc.z += a.z; acc.w += a.w;
    }
    float ic = 1.0f / (float)max(e - s, 1);
    acc.x *= ic; acc.y *= ic; acc.z *= ic; acc.w *= ic;
    store_a_quad(img_out, gw, lane, acc);
}

// ---------------- x -> fp16 image ----------------
__global__ void prep_x_kernel(const float* __restrict__ x,
                              __half* __restrict__ img, int N)
{
    int i = blockIdx.x * 256 + threadIdx.x;
    int node = i >> 5;
    int lane = i & 31;
    if (node >= N) return;
    float4 v = __ldg((const float4*)(x + (size_t)node * D + lane * 4));
    store_a_quad(img, node, lane, v);
}

// ---------------- weight prep (6 matrices, single fp16, one launch) --------
__global__ void prep_w_kernel(const float* W0, const float* W1, const float* W2,
                              const float* W3, const float* W4, const float* W5,
                              __half* __restrict__ wimg)
{
    int gi = blockIdx.x * 256 + threadIdx.x;
    if (gi >= 6 * 16384) return;
    int m = gi >> 14;
    int i = gi & 16383;
    const float* Ws[6] = {W0, W1, W2, W3, W4, W5};
    int k = i >> 7;
    int n = i & 127;
    float x = __ldg(Ws[m] + k * 128 + n);
    uint32_t byte = (uint32_t)(k >> 6) * 16384u + (uint32_t)(k & 63) * 256u
                  + ((uint32_t)((n >> 3) ^ (k & 7)) << 4) + (uint32_t)(n & 7) * 2u;
    __half* img = wimg + (size_t)m * 16384;
    img[byte >> 1] = __float2half(x);
}

// ---------------- HMMA GEMM: relu([mean|h] @ [Wl;Wr] + b), plain fp16 ------
// CTA: 128 rows x 128 cols, K=256 in 4 chunks of 64. 8 warps, warp = 32x64.
// 2-stage cp.async pipeline (32KB/stage) at 2 CTAs/SM.
#define GT 256
#define STG 32768          // per-stage: A 16K | W 16K
#define SM_TOT (2 * STG)

__global__ __launch_bounds__(GT, 2) void gemm_mma_kernel(
    const __half* __restrict__ ma, const __half* __restrict__ ha,
    const __half* __restrict__ wl, const __half* __restrict__ wr,
    const float* __restrict__ bias,
    __half* __restrict__ oimg, int N)
{
    extern __shared__ char smem[];
    const uint32_t sb = smem_u32(smem);
    const int t = threadIdx.x;
    const int lane = t & 31;
    const int w = t >> 5;
    const int wrow = (w & 3) * 32;
    const int wcol = (w >> 2) * 64;
    const int row0 = blockIdx.x * 128;

    const __half* as[2] = {ma, ha};
    const __half* ws[2] = {wl, wr};

    float C[64];
#pragma unroll
    for (int i = 0; i < 64; ++i) C[i] = 0.f;

    const int rsel = (lane & 7) + ((lane >> 3) & 1) * 8;
    const int usel = lane >> 4;

    // stage chunk c into buffer (c&1): A + W, 2048 x 16B cp.async
    auto stage_chunk = [&](int c) {
        const int mat = c >> 1, kh = c & 1;
        const char* sa = (const char*)as[mat] + (size_t)blockIdx.x * 32768 + kh * 16384;
        const char* sw = (const char*)ws[mat] + kh * 16384;
        uint32_t sbuf = sb + (uint32_t)(c & 1) * STG;
        for (int i = t; i < 2048; i += GT) {
            int which = i >> 10;
            uint32_t o = (uint32_t)(i & 1023) << 4;
            cp16(sbuf + (uint32_t)which * 16384u + o, (which ? sw : sa) + o);
        }
        asm volatile("cp.async.commit_group;" ::: "memory");
    };

    stage_chunk(0);

    for (int chunk = 0; chunk < 4; ++chunk) {
        if (chunk + 1 < 4) {
            stage_chunk(chunk + 1);
            asm volatile("cp.async.wait_group 1;" ::: "memory");
        } else {
            asm volatile("cp.async.wait_group 0;" ::: "memory");
        }
        __syncthreads();

        const uint32_t sa = sb + (uint32_t)(chunk & 1) * STG;   // A
        const uint32_t sw = sa + 16384u;                        // W

        // ---- compute: 4 k-steps of 16; 16 independent accumulators --------
#pragma unroll
        for (int ks = 0; ks < 4; ++ks) {
            const int k0 = ks * 16;
            uint32_t af[2][4];
#pragma unroll
            for (int mf = 0; mf < 2; ++mf) {
                int row = wrow + mf * 16 + rsel;
                uint32_t unit = (uint32_t)(((k0 >> 3) + usel) ^ (lane & 7));
                ldsm_x4(af[mf], sa + (uint32_t)row * 128u + (unit << 4));
            }
            uint32_t bf[4][4];
            const int krow = k0 + rsel;
#pragma unroll
            for (int nq = 0; nq < 4; ++nq) {
                const int n0 = wcol + nq * 16;
                uint32_t unit = (uint32_t)(((n0 >> 3) + usel) ^ (lane & 7));
                ldsm_x4_t(bf[nq], sw + (uint32_t)krow * 256u + (unit << 4));
            }
#pragma unroll
            for (int nq = 0; nq < 4; ++nq)
#pragma unroll
                for (int mf = 0; mf < 2; ++mf) {
                    mma_f16(&C[((mf * 8 + nq * 2) << 2)],     af[mf], bf[nq]);
                    mma_f16(&C[((mf * 8 + nq * 2 + 1) << 2)], af[mf], bf[nq] + 2);
                }
        }
        __syncthreads();   // buffer safe before restage (chunk+2)
    }

    // ---- epilogue: bias + relu -> fp16 image ----
#pragma unroll
    for (int mf = 0; mf < 2; ++mf) {
        int rloc = wrow + mf * 16 + (lane >> 2);
        int rlo = row0 + rloc;
#pragma unroll
        for (int nf = 0; nf < 8; ++nf) {
            int col = wcol + nf * 8 + (lane & 3) * 2;
            float b0 = __ldg(bias + col);
            float b1 = __ldg(bias + col + 1);
            const float* c = &C[((mf * 8 + nf) << 2)];
            float v0 = fmaxf(c[0] + b0, 0.f);
            float v1 = fmaxf(c[1] + b1, 0.f);
            float v2 = fmaxf(c[2] + b0, 0.f);
            float v3 = fmaxf(c[3] + b1, 0.f);
            if (rlo < N) {
                uint32_t byte = a_img_byte(blockIdx.x, col >> 6, rloc, col & 63);
                *(__half2*)((char*)oimg + byte) =
                    __halves2half2(__float2half(v0), __float2half(v1));
            }
            int rhi = rlo + 8;
            if (rhi < N) {
                uint32_t byte = a_img_byte(blockIdx.x, col >> 6, rloc + 8, col & 63);
                *(__half2*)((char*)oimg + byte) =
                    __halves2half2(__float2half(v2), __float2half(v3));
            }
        }
    }
}

// ---------------- pooled sum (sorted batch) from fp16 image + sigmoid head --
__global__ void pool_head_kernel(const __half* __restrict__ img,
                                 const int* __restrict__ batch,
                                 const float* __restrict__ Wro, const float* __restrict__ bro,
                                 float* __restrict__ out, int N)
{
    __shared__ int bounds[2];
    __shared__ float red[4];
    int g = blockIdx.x;
    int t = threadIdx.x;   // t = feature column 0..127

    if (t < 2) {
        int target = g + t;
        int lo = 0, hi = N;
        while (lo < hi) {
            int mid = (lo + hi) >> 1;
            if (batch[mid] < target) lo = mid + 1; else hi = mid;
        }
        bounds[t] = lo;
    }
    __syncthreads();
    int s = bounds[0], e = bounds[1];

    const int kh = t >> 6;
    const int kp = t & 63;
    const uint32_t ubase = (uint32_t)(kp >> 3);
    const uint32_t lodd  = (uint32_t)(kp & 7) << 1;

    float sum = 0.0f;
    for (int v = s; v < e; ++v) {
        int b = v >> 7, r = v & 127;
        uint32_t byte = (uint32_t)b * 32768u + (uint32_t)kh * 16384u
                      + (uint32_t)r * 128u
                      + ((ubase ^ (uint32_t)(r & 7)) << 4) + lodd;
        sum += __half2float(*(const __half*)((const char*)img + byte));
    }
    float val = sum * __ldg(&Wro[t]);
#pragma unroll
    for (int o = 16; o > 0; o >>= 1) val += __shfl_xor_sync(0xffffffff, val, o);
    if ((t & 31) == 0) red[t >> 5] = val;
    __syncthreads();
    if (t == 0) {
        float z = red[0] + red[1] + red[2] + red[3] + __ldg(bro);
        out[g] = 1.0f / (1.0f + expf(-z));
    }
}

// ---------------- launcher ----------------
extern "C" void kernel_launch(void* const* d_in, const int* in_sizes, int n_in,
                              void* d_out, int out_size)
{
    const float* x     = (const float*)d_in[0];
    const int*   ei    = (const int*)d_in[1];
    const int*   batch = (const int*)d_in[2];
    const float* Wl1 = (const float*)d_in[3];
    const float* Wr1 = (const float*)d_in[4];
    const float* b1  = (const float*)d_in[5];
    const float* Wl2 = (const float*)d_in[6];
    const float* Wr2 = (const float*)d_in[7];
    const float* b2  = (const float*)d_in[8];
    const float* Wl3 = (const float*)d_in[9];
    const float* Wr3 = (const float*)d_in[10];
    const float* b3  = (const float*)d_in[11];
    const float* Wro = (const float*)d_in[12];
    const float* bro = (const float*)d_in[13];
    float* out = (float*)d_out;

    int N = in_sizes[0] / D;
    int E = in_sizes[1] / 2;
    int G = out_size;

    int *cnt, *off, *cur, *srcs, *bsum;
    __half *wimg, *mimg, *ximg, *yimg;
    cudaGetSymbolAddress((void**)&cnt,  g_cnt);
    cudaGetSymbolAddress((void**)&off,  g_off);
    cudaGetSymbolAddress((void**)&cur,  g_cur);
    cudaGetSymbolAddress((void**)&srcs, g_src);
    cudaGetSymbolAddress((void**)&bsum, g_bsum);
    cudaGetSymbolAddress((void**)&wimg, g_wimg);
    cudaGetSymbolAddress((void**)&mimg, g_mimg);
    cudaGetSymbolAddress((void**)&ximg, g_ximg);
    cudaGetSymbolAddress((void**)&yimg, g_yimg);

    const int* src_arr = ei;
    const int* dst_arr = ei + E;

    // prep: weights (one launch) + x image
    prep_w_kernel<<<(6 * 16384 + 255) / 256, 256>>>(Wl1, Wr1, Wl2, Wr2, Wl3, Wr3, wimg);
    prep_x_kernel<<<(N * 32 + 255) / 256, 256>>>(x, ximg, N);

    // CSR build (parallel 3-phase scan)
    int nb = (N + 1023) / 1024;
    cudaMemsetAsync(cnt, 0, (size_t)N * sizeof(int));
    count_kernel<<<(E + 255) / 256, 256>>>(dst_arr, cnt, E);
    bsum_kernel<<<nb, 1024>>>(cnt, bsum, N);
    scan_bsum_kernel<<<1, 1024>>>(bsum, off, nb, N);
    scan_final_kernel<<<nb, 1024>>>(cnt, bsum, off, cur, N);
    fill_kernel<<<(E + 255) / 256, 256>>>(src_arr, dst_arr, cur, srcs, E);

    cudaFuncSetAttribute((const void*)gemm_mma_kernel,
                         cudaFuncAttributeMaxDynamicSharedMemorySize, SM_TOT);
    int gblocks = (N + 127) / 128;
    int ablocks = (N * 32 + 255) / 256;

    __half* im = wimg;
    // layer 1: agg from x image, gemm -> y image
    agg_kernel<<<ablocks, 256>>>(ximg, mimg, off, srcs, N);
    gemm_mma_kernel<<<gblocks, GT, SM_TOT>>>(mimg, ximg,
        im + 0 * 16384, im + 1 * 16384, b1, yimg, N);
    // layer 2: agg from y image, gemm -> x image
    agg_kernel<<<ablocks, 256>>>(yimg, mimg, off, srcs, N);
    gemm_mma_kernel<<<gblocks, GT, SM_TOT>>>(mimg, yimg,
        im + 2 * 16384, im + 3 * 16384, b2, ximg, N);
    // layer 3: agg from x image, gemm -> y image
    agg_kernel<<<ablocks, 256>>>(ximg, mimg, off, srcs, N);
    gemm_mma_kernel<<<gblocks, GT, SM_TOT>>>(mimg, ximg,
        im + 4 * 16384, im + 5 * 16384, b3, yimg, N);

    // pooling + head (reads fp16 image)
    pool_head_kernel<<<G, D>>>(yimg, batch, Wro, bro, out, N);
}